// round 2
// baseline (speedup 1.0000x reference)
#include <cuda_runtime.h>
#include <math.h>
#include <stdint.h>

#define BB     16
#define CC     256
#define HH     64
#define WWID   64
#define PP     4096   // HH*WWID
#define TT     1024   // 32*32 pooled tokens
#define NHEADS 8
#define DHEAD  32

// ---------------- scratch (device globals; no allocs allowed) ----------------
__device__ float         g_pooled[BB*CC*TT];           // [b][c][t]
__device__ unsigned char g_idx   [BB*CC*TT];           // argmax 0..3
__device__ float         g_q   [BB*NHEADS*DHEAD*TT];   // [bh][dhi][t]
__device__ float         g_k   [BB*NHEADS*DHEAD*TT];
__device__ float         g_v   [BB*NHEADS*DHEAD*TT];
__device__ float         g_attn[BB*NHEADS*DHEAD*TT];   // [bh][dhi][t]
__device__ float         g_proj[BB*CC*TT];             // [b][c][t], pre-scaled by tanh(gamma)

// =====================================================================
// Kernel 1: 1x1 conv (feature reduce) + bias + 2x2 maxpool with indices
// =====================================================================
__global__ __launch_bounds__(256) void k_fr_pool(
    const float* __restrict__ x, const float* __restrict__ frw,
    const float* __restrict__ frb)
{
    __shared__ float Xs[32][128];
    __shared__ float Ws[64][32];
    int tid = threadIdx.x;
    int hp = blockIdx.x, ocT = blockIdx.y, b = blockIdx.z;
    int oc0 = ocT * 64;
    int ocg = tid >> 5;       // 0..7 -> 8 oc each
    int pxg = tid & 31;       // 0..31 -> 4 px each

    float acc[8][4];
#pragma unroll
    for (int i = 0; i < 8; i++)
#pragma unroll
        for (int j = 0; j < 4; j++) acc[i][j] = 0.f;

    const float* xb = x + (size_t)b*CC*PP + hp*128;   // rows 2hp,2hp+1 contiguous

    for (int c0 = 0; c0 < CC; c0 += 32) {
#pragma unroll
        for (int j = 0; j < 4; j++) {
            int f = tid + j*256;              // float4 index 0..1023
            int k = f >> 5, c4 = f & 31;
            *(float4*)&Xs[k][c4*4] = *(const float4*)(xb + (size_t)(c0+k)*PP + c4*4);
        }
#pragma unroll
        for (int j = 0; j < 8; j++) {
            int f = tid + j*256;              // 0..2047
            int oc = f >> 5, k = f & 31;
            Ws[oc][k] = frw[(size_t)(oc0+oc)*CC + c0 + k];
        }
        __syncthreads();
#pragma unroll 8
        for (int k = 0; k < 32; k++) {
            float4 xv = *(const float4*)&Xs[k][pxg*4];
#pragma unroll
            for (int i = 0; i < 8; i++) {
                float w = Ws[ocg*8+i][k];     // broadcast within warp
                acc[i][0] = fmaf(w, xv.x, acc[i][0]);
                acc[i][1] = fmaf(w, xv.y, acc[i][1]);
                acc[i][2] = fmaf(w, xv.z, acc[i][2]);
                acc[i][3] = fmaf(w, xv.w, acc[i][3]);
            }
        }
        __syncthreads();
    }

    bool low = (pxg < 16);
#pragma unroll
    for (int i = 0; i < 8; i++) {
        int oc = oc0 + ocg*8 + i;
        float bi = frb[oc];
        float a0 = acc[i][0]+bi, a1 = acc[i][1]+bi;
        float a2 = acc[i][2]+bi, a3 = acc[i][3]+bi;
        float p0 = __shfl_xor_sync(0xffffffffu, a0, 16);
        float p1 = __shfl_xor_sync(0xffffffffu, a1, 16);
        float p2 = __shfl_xor_sync(0xffffffffu, a2, 16);
        float p3 = __shfl_xor_sync(0xffffffffu, a3, 16);
        if (low) {
            size_t base = ((size_t)b*CC + oc)*TT + hp*32 + pxg*2;
            {   float best = a0; int am = 0;
                if (a1 > best) { best = a1; am = 1; }
                if (p0 > best) { best = p0; am = 2; }
                if (p1 > best) { best = p1; am = 3; }
                g_pooled[base] = best; g_idx[base] = (unsigned char)am; }
            {   float best = a2; int am = 0;
                if (a3 > best) { best = a3; am = 1; }
                if (p2 > best) { best = p2; am = 2; }
                if (p3 > best) { best = p3; am = 3; }
                g_pooled[base+1] = best; g_idx[base+1] = (unsigned char)am; }
        }
    }
}

// =====================================================================
// Kernel 2: QKV projection
// =====================================================================
__global__ __launch_bounds__(256) void k_qkv(
    const float* __restrict__ wq, const float* __restrict__ wk,
    const float* __restrict__ wv)
{
    __shared__ float As[32][64];
    __shared__ float Bq[32][64], Bk[32][64], Bv[32][64];
    int tid = threadIdx.x;
    int t0 = blockIdx.x*64, d0 = blockIdx.y*64, b = blockIdx.z;
    int ng = tid & 15, mg = tid >> 4;

    float aq[4][4], ak[4][4], av[4][4];
#pragma unroll
    for (int i = 0; i < 4; i++)
#pragma unroll
        for (int j = 0; j < 4; j++) { aq[i][j]=0.f; ak[i][j]=0.f; av[i][j]=0.f; }

    const float* pb = g_pooled + (size_t)b*CC*TT;

    for (int c0 = 0; c0 < CC; c0 += 32) {
#pragma unroll
        for (int j = 0; j < 2; j++) {
            int f = tid + j*256;              // f4 idx 0..511
            int k = f >> 4, m4 = f & 15;
            *(float4*)&As[k][m4*4] = *(const float4*)(pb + (size_t)(c0+k)*TT + t0 + m4*4);
            *(float4*)&Bq[k][m4*4] = *(const float4*)(wq + (size_t)(c0+k)*CC + d0 + m4*4);
            *(float4*)&Bk[k][m4*4] = *(const float4*)(wk + (size_t)(c0+k)*CC + d0 + m4*4);
            *(float4*)&Bv[k][m4*4] = *(const float4*)(wv + (size_t)(c0+k)*CC + d0 + m4*4);
        }
        __syncthreads();
#pragma unroll 8
        for (int k = 0; k < 32; k++) {
            float4 a  = *(const float4*)&As[k][mg*4];
            float4 q4 = *(const float4*)&Bq[k][ng*4];
            float4 k4 = *(const float4*)&Bk[k][ng*4];
            float4 v4 = *(const float4*)&Bv[k][ng*4];
            float am[4] = {a.x,a.y,a.z,a.w};
            float qn[4] = {q4.x,q4.y,q4.z,q4.w};
            float kn[4] = {k4.x,k4.y,k4.z,k4.w};
            float vn[4] = {v4.x,v4.y,v4.z,v4.w};
#pragma unroll
            for (int mm = 0; mm < 4; mm++)
#pragma unroll
                for (int nn = 0; nn < 4; nn++) {
                    aq[mm][nn] = fmaf(am[mm], qn[nn], aq[mm][nn]);
                    ak[mm][nn] = fmaf(am[mm], kn[nn], ak[mm][nn]);
                    av[mm][nn] = fmaf(am[mm], vn[nn], av[mm][nn]);
                }
        }
        __syncthreads();
    }

#pragma unroll
    for (int nn = 0; nn < 4; nn++) {
        int d = d0 + ng*4 + nn;
        int head = d & 7, dhi = d >> 3;
        size_t base = (((size_t)b*NHEADS + head)*DHEAD + dhi)*TT + t0 + mg*4;
        *(float4*)&g_q[base] = make_float4(aq[0][nn], aq[1][nn], aq[2][nn], aq[3][nn]);
        *(float4*)&g_k[base] = make_float4(ak[0][nn], ak[1][nn], ak[2][nn], ak[3][nn]);
        *(float4*)&g_v[base] = make_float4(av[0][nn], av[1][nn], av[2][nn], av[3][nn]);
    }
}

// =====================================================================
// Kernel 3: flash attention
// =====================================================================
__global__ __launch_bounds__(256) void k_attn()
{
    __shared__ float Qs[32][64];
    __shared__ float Ks[32][64];
    __shared__ float Vs[64][36];
    __shared__ float Ps[64][65];
    __shared__ float m_s[64], l_s[64], al_s[64];

    int tid = threadIdx.x;
    int q0 = blockIdx.x*64; int bh = blockIdx.y;
    const float* Qg = g_q + (size_t)bh*DHEAD*TT;
    const float* Kg = g_k + (size_t)bh*DHEAD*TT;
    const float* Vg = g_v + (size_t)bh*DHEAD*TT;
    const float qscale = 0.17677669529663687f;  // 1/sqrt(32)

#pragma unroll
    for (int j = 0; j < 2; j++) {
        int f = tid + j*256;
        int dhi = f >> 4, t4 = f & 15;
        float4 v = *(const float4*)(Qg + (size_t)dhi*TT + q0 + t4*4);
        v.x *= qscale; v.y *= qscale; v.z *= qscale; v.w *= qscale;
        *(float4*)&Qs[dhi][t4*4] = v;
    }
    if (tid < 64) { m_s[tid] = -3.0e38f; l_s[tid] = 0.f; }

    float o[8];
#pragma unroll
    for (int d = 0; d < 8; d++) o[d] = 0.f;

    int qig = tid >> 3, kjg = tid & 7;
    int qo  = tid & 63, dhg = tid >> 6;
    __syncthreads();

    for (int k0 = 0; k0 < TT; k0 += 64) {
#pragma unroll
        for (int j = 0; j < 2; j++) {
            int f = tid + j*256;
            int dhi = f >> 4, t4 = f & 15;
            *(float4*)&Ks[dhi][t4*4] = *(const float4*)(Kg + (size_t)dhi*TT + k0 + t4*4);
            float4 v = *(const float4*)(Vg + (size_t)dhi*TT + k0 + t4*4);
            Vs[t4*4+0][dhi] = v.x; Vs[t4*4+1][dhi] = v.y;
            Vs[t4*4+2][dhi] = v.z; Vs[t4*4+3][dhi] = v.w;
        }
        __syncthreads();

        float s[2][8];
#pragma unroll
        for (int i = 0; i < 2; i++)
#pragma unroll
            for (int j = 0; j < 8; j++) s[i][j] = 0.f;
#pragma unroll 8
        for (int dhi = 0; dhi < 32; dhi++) {
            float q0v = Qs[dhi][qig*2+0];
            float q1v = Qs[dhi][qig*2+1];
            float4 ka = *(const float4*)&Ks[dhi][kjg*8];
            float4 kb = *(const float4*)&Ks[dhi][kjg*8+4];
            float kv[8] = {ka.x,ka.y,ka.z,ka.w,kb.x,kb.y,kb.z,kb.w};
#pragma unroll
            for (int j = 0; j < 8; j++) {
                s[0][j] = fmaf(q0v, kv[j], s[0][j]);
                s[1][j] = fmaf(q1v, kv[j], s[1][j]);
            }
        }

        float mnew[2], alp[2], csum[2];
#pragma unroll
        for (int i = 0; i < 2; i++) {
            float m = s[i][0];
#pragma unroll
            for (int j = 1; j < 8; j++) m = fmaxf(m, s[i][j]);
            m = fmaxf(m, __shfl_xor_sync(0xffffffffu, m, 4));
            m = fmaxf(m, __shfl_xor_sync(0xffffffffu, m, 2));
            m = fmaxf(m, __shfl_xor_sync(0xffffffffu, m, 1));
            int qi = qig*2 + i;
            float mold = m_s[qi];
            mnew[i] = fmaxf(mold, m);
            alp[i]  = __expf(mold - mnew[i]);
            float cs = 0.f;
#pragma unroll
            for (int j = 0; j < 8; j++) {
                float p = __expf(s[i][j] - mnew[i]);
                Ps[qi][kjg*8+j] = p;
                cs += p;
            }
            cs += __shfl_xor_sync(0xffffffffu, cs, 4);
            cs += __shfl_xor_sync(0xffffffffu, cs, 2);
            cs += __shfl_xor_sync(0xffffffffu, cs, 1);
            csum[i] = cs;
        }
        if (kjg == 0) {
#pragma unroll
            for (int i = 0; i < 2; i++) {
                int qi = qig*2 + i;
                m_s[qi]  = mnew[i];
                l_s[qi]  = l_s[qi]*alp[i] + csum[i];
                al_s[qi] = alp[i];
            }
        }
        __syncthreads();

        float alpha = al_s[qo];
#pragma unroll
        for (int d = 0; d < 8; d++) o[d] *= alpha;
#pragma unroll 4
        for (int kj = 0; kj < 64; kj++) {
            float p = Ps[qo][kj];
            float4 va = *(const float4*)&Vs[kj][dhg*8];
            float4 vb = *(const float4*)&Vs[kj][dhg*8+4];
            o[0] = fmaf(p, va.x, o[0]); o[1] = fmaf(p, va.y, o[1]);
            o[2] = fmaf(p, va.z, o[2]); o[3] = fmaf(p, va.w, o[3]);
            o[4] = fmaf(p, vb.x, o[4]); o[5] = fmaf(p, vb.y, o[5]);
            o[6] = fmaf(p, vb.z, o[6]); o[7] = fmaf(p, vb.w, o[7]);
        }
        __syncthreads();
    }

    float linv = 1.f / l_s[qo];
    float* Og = g_attn + (size_t)bh*DHEAD*TT;
#pragma unroll
    for (int d = 0; d < 8; d++)
        Og[(size_t)(dhg*8+d)*TT + q0 + qo] = o[d]*linv;
}

// =====================================================================
// Kernel 4: output projection, scaled by tanh(gamma)
// =====================================================================
__global__ __launch_bounds__(256) void k_proj(
    const float* __restrict__ wo, const float* __restrict__ gamma)
{
    __shared__ float As[32][64];
    __shared__ float Bs[32][64];
    int tid = threadIdx.x;
    int t0 = blockIdx.x*64, d0 = blockIdx.y*64, b = blockIdx.z;
    int ng = tid & 15, mg = tid >> 4;

    float acc[4][4];
#pragma unroll
    for (int i = 0; i < 4; i++)
#pragma unroll
        for (int j = 0; j < 4; j++) acc[i][j] = 0.f;

    for (int c0 = 0; c0 < CC; c0 += 32) {
#pragma unroll
        for (int j = 0; j < 2; j++) {
            int f = tid + j*256;
            int k = f >> 4, m4 = f & 15;
            int d = c0 + k;
            const float* src = g_attn + (((size_t)b*NHEADS + (d&7))*DHEAD + (d>>3))*TT + t0 + m4*4;
            *(float4*)&As[k][m4*4] = *(const float4*)src;
            *(float4*)&Bs[k][m4*4] = *(const float4*)(wo + (size_t)d*CC + d0 + m4*4);
        }
        __syncthreads();
#pragma unroll 8
        for (int k = 0; k < 32; k++) {
            float4 a  = *(const float4*)&As[k][mg*4];
            float4 bv = *(const float4*)&Bs[k][ng*4];
            float am[4] = {a.x,a.y,a.z,a.w};
            float bn[4] = {bv.x,bv.y,bv.z,bv.w};
#pragma unroll
            for (int mm = 0; mm < 4; mm++)
#pragma unroll
                for (int nn = 0; nn < 4; nn++)
                    acc[mm][nn] = fmaf(am[mm], bn[nn], acc[mm][nn]);
        }
        __syncthreads();
    }

    float tg = tanhf(gamma[0]);
#pragma unroll
    for (int nn = 0; nn < 4; nn++) {
        int d = d0 + ng*4 + nn;
        size_t base = ((size_t)b*CC + d)*TT + t0 + mg*4;
        *(float4*)&g_proj[base] =
            make_float4(acc[0][nn]*tg, acc[1][nn]*tg, acc[2][nn]*tg, acc[3][nn]*tg);
    }
}

// =====================================================================
// Kernel 5: conv3x3 via tf32 mma.sync (implicit GEMM) + bias + unpool-add.
// Block: 8 warps. Tile: 8 image rows x 64 cols x 64 oc.
// Warp: 1 row x 64 px (4 m16 tiles) x 64 oc (8 n8 tiles).
// Grid (8 rowT, 4 ocT, 16 b).
// =====================================================================
__device__ __forceinline__ float to_tf32(float v) {
    uint32_t u;
    asm("cvt.rna.tf32.f32 %0, %1;" : "=r"(u) : "f"(v));
    return __uint_as_float(u);
}

__device__ __forceinline__ void mma_tf32(float4& c, const uint32_t* a, uint2 b) {
    asm volatile(
        "mma.sync.aligned.m16n8k8.row.col.f32.tf32.tf32.f32 "
        "{%0,%1,%2,%3}, {%4,%5,%6,%7}, {%8,%9}, {%0,%1,%2,%3};"
        : "+f"(c.x), "+f"(c.y), "+f"(c.z), "+f"(c.w)
        : "r"(a[0]), "r"(a[1]), "r"(a[2]), "r"(a[3]), "r"(b.x), "r"(b.y));
}

// Xs: [10 halo rows][66 halo cols][ic-pair interleave 8]  (row stride 528, col stride 8)
//     element (p,hi) at col offset p*2+hi holds ic = p + hi*4   -> a0/a2 = one float2
// Ws: [9 taps][4 p][68 oc][2 hi]  (tap stride 544, p stride 136, oc stride 2)
// Cs (epilogue union): per-warp [16 px][72 oc]
union ConvSmem {
    struct { float Xs[10*528]; float Ws[9*544]; } m;   // 40704 B
    float Cs[8][16*72];                                 // 36864 B
};

__global__ __launch_bounds__(256, 1) void k_conv3_mma(
    const float* __restrict__ x, const float* __restrict__ cw,
    const float* __restrict__ cb, float* __restrict__ out)
{
    __shared__ ConvSmem sm;
    int tid  = threadIdx.x;
    int w    = tid >> 5, lane = tid & 31;
    int g    = lane >> 2, tig = lane & 3;
    int rowT = blockIdx.x, ocT = blockIdx.y, b = blockIdx.z;
    int oc0  = ocT * 64;
    int row0 = rowT * 8;

    float4 c[4][8];
#pragma unroll
    for (int m = 0; m < 4; m++)
#pragma unroll
        for (int n = 0; n < 8; n++) c[m][n] = make_float4(0.f,0.f,0.f,0.f);

    for (int ic0 = 0; ic0 < CC; ic0 += 8) {
        __syncthreads();
        // ---- stage Xs (8 ic x 10 rows x 66 cols, zero-padded halo, tf32-rounded)
        for (int idx = tid; idx < 5280; idx += 256) {
            int ic  = idx / 660;
            int rem = idx - ic*660;
            int rr  = rem / 66, ccx = rem - rr*66;
            int gy  = row0 - 1 + rr, gc = ccx - 1;
            float v = 0.f;
            if ((unsigned)gy < 64u && (unsigned)gc < 64u)
                v = x[((size_t)(b*CC + ic0 + ic))*PP + gy*64 + gc];
            sm.m.Xs[rr*528 + ccx*8 + (ic&3)*2 + (ic>>2)] = to_tf32(v);
        }
        // ---- stage Ws (64 oc x contiguous 72 floats = 8 ic x 9 taps)
        for (int f = tid; f < 4608; f += 256) {
            int oc = f / 72, r = f - oc*72;
            int ic = r / 9, tap = r - ic*9;
            float v = cw[(size_t)(oc0+oc)*2304 + ic0*9 + r];
            sm.m.Ws[tap*544 + (ic&3)*136 + oc*2 + (ic>>2)] = to_tf32(v);
        }
        __syncthreads();

        // ---- compute: 9 taps x (4 m-tiles x 8 n-tiles) mma per warp
#pragma unroll
        for (int kh = 0; kh < 3; kh++) {
            const float* Xr = sm.m.Xs + (w + kh)*528;
#pragma unroll
            for (int kw = 0; kw < 3; kw++) {
                const float* Wt = sm.m.Ws + (kh*3+kw)*544 + tig*136;
                uint2 bf[8];
#pragma unroll
                for (int n = 0; n < 8; n++) {
                    float2 bb = *(const float2*)(Wt + n*16 + g*2);
                    bf[n] = make_uint2(__float_as_uint(bb.x), __float_as_uint(bb.y));
                }
#pragma unroll
                for (int m = 0; m < 4; m++) {
                    const float* base = Xr + (m*16 + g + kw)*8 + tig*2;
                    float2 lo = *(const float2*)(base);        // rows g
                    float2 hi = *(const float2*)(base + 64);   // rows g+8
                    uint32_t a[4] = {__float_as_uint(lo.x), __float_as_uint(hi.x),
                                     __float_as_uint(lo.y), __float_as_uint(hi.y)};
#pragma unroll
                    for (int n = 0; n < 8; n++) mma_tf32(c[m][n], a, bf[n]);
                }
            }
        }
    }

    // ---- epilogue: transpose through smem, bias + unpool-gated add, float4 stores
    __syncthreads();
    int gy   = row0 + w;
    int h2   = gy >> 1;
    int subr = (gy & 1) << 1;
    float* Cw = sm.Cs[w];

#pragma unroll 1
    for (int m = 0; m < 4; m++) {
        __syncwarp();
#pragma unroll
        for (int n = 0; n < 8; n++) {
            *(float2*)(Cw + g*72 + n*8 + tig*2)     = make_float2(c[m][n].x, c[m][n].y);
            *(float2*)(Cw + (g+8)*72 + n*8 + tig*2) = make_float2(c[m][n].z, c[m][n].w);
        }
        __syncwarp();
#pragma unroll
        for (int rep = 0; rep < 2; rep++) {
            int oc_l = rep*32 + lane;
            int oc   = oc0 + oc_l;
            size_t chan = (size_t)b*CC + oc;
            float bias = cb[oc];
            const unsigned char* idxp  = g_idx  + chan*TT + (size_t)h2*32 + m*8;
            const float*         projp = g_proj + chan*TT + (size_t)h2*32 + m*8;
            float vout[16];
#pragma unroll
            for (int px = 0; px < 16; px++) {
                float v = Cw[px*72 + oc_l] + bias;
                if (idxp[px>>1] == (unsigned char)(subr | (px & 1)))
                    v += projp[px>>1];
                vout[px] = v;
            }
            float* op = out + chan*PP + (size_t)gy*64 + m*16;
            *(float4*)(op+0)  = make_float4(vout[0], vout[1], vout[2], vout[3]);
            *(float4*)(op+4)  = make_float4(vout[4], vout[5], vout[6], vout[7]);
            *(float4*)(op+8)  = make_float4(vout[8], vout[9], vout[10],vout[11]);
            *(float4*)(op+12) = make_float4(vout[12],vout[13],vout[14],vout[15]);
        }
    }
}

// =====================================================================
extern "C" void kernel_launch(void* const* d_in, const int* in_sizes, int n_in,
                              void* d_out, int out_size)
{
    const float* x      = (const float*)d_in[0];
    const float* conv_w = (const float*)d_in[1];
    const float* conv_b = (const float*)d_in[2];
    const float* fr_w   = (const float*)d_in[3];
    const float* fr_b   = (const float*)d_in[4];
    const float* wq     = (const float*)d_in[5];
    const float* wk     = (const float*)d_in[6];
    const float* wv     = (const float*)d_in[7];
    const float* wo     = (const float*)d_in[8];
    const float* gamma  = (const float*)d_in[9];
    float* out = (float*)d_out;

    k_fr_pool   <<<dim3(32, 4, BB),        256>>>(x, fr_w, fr_b);
    k_qkv       <<<dim3(16, 4, BB),        256>>>(wq, wk, wv);
    k_attn      <<<dim3(16, BB*NHEADS, 1), 256>>>();
    k_proj      <<<dim3(16, 4, BB),        256>>>(wo, gamma);
    k_conv3_mma <<<dim3(8, 4, BB),         256>>>(x, conv_w, conv_b, out);
}

// round 6
// speedup vs baseline: 1.2927x; 1.2927x over previous
#include <cuda_runtime.h>
#include <math.h>
#include <stdint.h>

#define BB     16
#define CC     256
#define HH     64
#define WWID   64
#define PP     4096   // HH*WWID
#define TT     1024   // 32*32 pooled tokens
#define NHEADS 8
#define DHEAD  32

typedef unsigned long long u64;

// ---------------- packed fp32 helpers (sm_100 base ISA) ----------------
__device__ __forceinline__ u64 pk2(float lo, float hi) {
    u64 r; asm("mov.b64 %0, {%1,%2};" : "=l"(r) : "f"(lo), "f"(hi)); return r;
}
__device__ __forceinline__ u64 dup2(float v) { return pk2(v, v); }
__device__ __forceinline__ void fma2(u64& acc, u64 a, u64 b) {
    asm("fma.rn.f32x2 %0, %1, %2, %0;" : "+l"(acc) : "l"(a), "l"(b));
}
__device__ __forceinline__ void mul2(u64& acc, u64 a) {
    asm("mul.rn.f32x2 %0, %0, %1;" : "+l"(acc) : "l"(a));
}
__device__ __forceinline__ float2 up2(u64 v) {
    float2 f; asm("mov.b64 {%0,%1}, %2;" : "=f"(f.x), "=f"(f.y) : "l"(v)); return f;
}
__device__ __forceinline__ const u64* as_u64(const float* p) { return (const u64*)p; }

// ---------------- scratch (device globals; no allocs allowed) ----------------
__device__ float         g_pooled[BB*CC*TT];           // [b][c][t]
__device__ unsigned char g_idx   [BB*CC*TT];           // argmax 0..3
__device__ float         g_q   [BB*NHEADS*DHEAD*TT];   // [bh][dhi][t]
__device__ float         g_k   [BB*NHEADS*DHEAD*TT];
__device__ float         g_v   [BB*NHEADS*DHEAD*TT];
__device__ float         g_attn[BB*NHEADS*DHEAD*TT];   // [bh][dhi][t]
__device__ float         g_proj[BB*CC*TT];             // [b][c][t], pre-scaled by tanh(gamma)

// =====================================================================
// Kernel 1: 1x1 conv (feature reduce) + bias + 2x2 maxpool with indices
// f32x2: acc pairs along px; W staged duplicated (w,w) -> broadcast LDS.64
// =====================================================================
__global__ __launch_bounds__(256) void k_fr_pool(
    const float* __restrict__ x, const float* __restrict__ frw,
    const float* __restrict__ frb)
{
    __shared__ float  Xs[32][128];
    __shared__ float2 Wd[64][32];
    int tid = threadIdx.x;
    int hp = blockIdx.x, ocT = blockIdx.y, b = blockIdx.z;
    int oc0 = ocT * 64;
    int ocg = tid >> 5;       // warp id 0..7 -> 8 oc each (warp-uniform)
    int pxg = tid & 31;       // 4 px each

    u64 acc[8][2];
#pragma unroll
    for (int i = 0; i < 8; i++) { acc[i][0] = 0ull; acc[i][1] = 0ull; }

    const float* xb = x + (size_t)b*CC*PP + hp*128;

    for (int c0 = 0; c0 < CC; c0 += 32) {
#pragma unroll
        for (int j = 0; j < 4; j++) {
            int f = tid + j*256;
            int k = f >> 5, c4 = f & 31;
            *(float4*)&Xs[k][c4*4] = *(const float4*)(xb + (size_t)(c0+k)*PP + c4*4);
        }
#pragma unroll
        for (int j = 0; j < 8; j++) {
            int f = tid + j*256;
            int oc = f >> 5, k = f & 31;
            float v = frw[(size_t)(oc0+oc)*CC + c0 + k];
            Wd[oc][k] = make_float2(v, v);
        }
        __syncthreads();
#pragma unroll 8
        for (int k = 0; k < 32; k++) {
            u64 xa = as_u64(&Xs[k][pxg*4])[0];
            u64 xb2 = as_u64(&Xs[k][pxg*4])[1];
#pragma unroll
            for (int i = 0; i < 8; i++) {
                u64 w = *(const u64*)&Wd[ocg*8+i][k];   // broadcast
                fma2(acc[i][0], w, xa);
                fma2(acc[i][1], w, xb2);
            }
        }
        __syncthreads();
    }

    bool low = (pxg < 16);
#pragma unroll
    for (int i = 0; i < 8; i++) {
        int oc = oc0 + ocg*8 + i;
        float bi = frb[oc];
        float2 lo = up2(acc[i][0]);
        float2 hi = up2(acc[i][1]);
        float a0 = lo.x+bi, a1 = lo.y+bi, a2 = hi.x+bi, a3 = hi.y+bi;
        float p0 = __shfl_xor_sync(0xffffffffu, a0, 16);
        float p1 = __shfl_xor_sync(0xffffffffu, a1, 16);
        float p2 = __shfl_xor_sync(0xffffffffu, a2, 16);
        float p3 = __shfl_xor_sync(0xffffffffu, a3, 16);
        if (low) {
            size_t base = ((size_t)b*CC + oc)*TT + hp*32 + pxg*2;
            {   float best = a0; int am = 0;
                if (a1 > best) { best = a1; am = 1; }
                if (p0 > best) { best = p0; am = 2; }
                if (p1 > best) { best = p1; am = 3; }
                g_pooled[base] = best; g_idx[base] = (unsigned char)am; }
            {   float best = a2; int am = 0;
                if (a3 > best) { best = a3; am = 1; }
                if (p2 > best) { best = p2; am = 2; }
                if (p3 > best) { best = p3; am = 3; }
                g_pooled[base+1] = best; g_idx[base+1] = (unsigned char)am; }
        }
    }
}

// =====================================================================
// Kernel 2: QKV projection (f32x2: n-pairs from B tiles; a dup'd, shared x3)
// =====================================================================
__global__ __launch_bounds__(256) void k_qkv(
    const float* __restrict__ wq, const float* __restrict__ wk,
    const float* __restrict__ wv)
{
    __shared__ float As[32][64];
    __shared__ float Bq[32][64], Bk[32][64], Bv[32][64];
    int tid = threadIdx.x;
    int t0 = blockIdx.x*64, d0 = blockIdx.y*64, b = blockIdx.z;
    int ng = tid & 15, mg = tid >> 4;

    u64 aq[4][2], ak[4][2], av[4][2];
#pragma unroll
    for (int i = 0; i < 4; i++)
#pragma unroll
        for (int j = 0; j < 2; j++) { aq[i][j]=0ull; ak[i][j]=0ull; av[i][j]=0ull; }

    const float* pb = g_pooled + (size_t)b*CC*TT;

    for (int c0 = 0; c0 < CC; c0 += 32) {
#pragma unroll
        for (int j = 0; j < 2; j++) {
            int f = tid + j*256;
            int k = f >> 4, m4 = f & 15;
            *(float4*)&As[k][m4*4] = *(const float4*)(pb + (size_t)(c0+k)*TT + t0 + m4*4);
            *(float4*)&Bq[k][m4*4] = *(const float4*)(wq + (size_t)(c0+k)*CC + d0 + m4*4);
            *(float4*)&Bk[k][m4*4] = *(const float4*)(wk + (size_t)(c0+k)*CC + d0 + m4*4);
            *(float4*)&Bv[k][m4*4] = *(const float4*)(wv + (size_t)(c0+k)*CC + d0 + m4*4);
        }
        __syncthreads();
#pragma unroll 8
        for (int k = 0; k < 32; k++) {
            float4 a = *(const float4*)&As[k][mg*4];
            u64 am[4] = {dup2(a.x), dup2(a.y), dup2(a.z), dup2(a.w)};
            u64 bq0 = as_u64(&Bq[k][ng*4])[0], bq1 = as_u64(&Bq[k][ng*4])[1];
            u64 bk0 = as_u64(&Bk[k][ng*4])[0], bk1 = as_u64(&Bk[k][ng*4])[1];
            u64 bv0 = as_u64(&Bv[k][ng*4])[0], bv1 = as_u64(&Bv[k][ng*4])[1];
#pragma unroll
            for (int mm = 0; mm < 4; mm++) {
                fma2(aq[mm][0], am[mm], bq0); fma2(aq[mm][1], am[mm], bq1);
                fma2(ak[mm][0], am[mm], bk0); fma2(ak[mm][1], am[mm], bk1);
                fma2(av[mm][0], am[mm], bv0); fma2(av[mm][1], am[mm], bv1);
            }
        }
        __syncthreads();
    }

#pragma unroll
    for (int np = 0; np < 2; np++) {
        float2 q_[4], k_[4], v_[4];
#pragma unroll
        for (int mm = 0; mm < 4; mm++) {
            q_[mm] = up2(aq[mm][np]); k_[mm] = up2(ak[mm][np]); v_[mm] = up2(av[mm][np]);
        }
#pragma unroll
        for (int sub = 0; sub < 2; sub++) {
            int d = d0 + ng*4 + np*2 + sub;
            int head = d & 7, dhi = d >> 3;
            size_t base = (((size_t)b*NHEADS + head)*DHEAD + dhi)*TT + t0 + mg*4;
            if (sub == 0) {
                *(float4*)&g_q[base] = make_float4(q_[0].x, q_[1].x, q_[2].x, q_[3].x);
                *(float4*)&g_k[base] = make_float4(k_[0].x, k_[1].x, k_[2].x, k_[3].x);
                *(float4*)&g_v[base] = make_float4(v_[0].x, v_[1].x, v_[2].x, v_[3].x);
            } else {
                *(float4*)&g_q[base] = make_float4(q_[0].y, q_[1].y, q_[2].y, q_[3].y);
                *(float4*)&g_k[base] = make_float4(k_[0].y, k_[1].y, k_[2].y, k_[3].y);
                *(float4*)&g_v[base] = make_float4(v_[0].y, v_[1].y, v_[2].y, v_[3].y);
            }
        }
    }
}

// =====================================================================
// Kernel 3: flash attention (f32x2 in S and O loops)
// =====================================================================
__global__ __launch_bounds__(256) void k_attn()
{
    __shared__ float Qs[32][64];
    __shared__ float Ks[32][64];
    __shared__ float Vs[64][36];
    __shared__ float Ps[64][65];
    __shared__ float m_s[64], l_s[64], al_s[64];

    int tid = threadIdx.x;
    int q0 = blockIdx.x*64; int bh = blockIdx.y;
    const float* Qg = g_q + (size_t)bh*DHEAD*TT;
    const float* Kg = g_k + (size_t)bh*DHEAD*TT;
    const float* Vg = g_v + (size_t)bh*DHEAD*TT;
    const float qscale = 0.17677669529663687f;

#pragma unroll
    for (int j = 0; j < 2; j++) {
        int f = tid + j*256;
        int dhi = f >> 4, t4 = f & 15;
        float4 v = *(const float4*)(Qg + (size_t)dhi*TT + q0 + t4*4);
        v.x *= qscale; v.y *= qscale; v.z *= qscale; v.w *= qscale;
        *(float4*)&Qs[dhi][t4*4] = v;
    }
    if (tid < 64) { m_s[tid] = -3.0e38f; l_s[tid] = 0.f; }

    u64 o2[4];
#pragma unroll
    for (int d = 0; d < 4; d++) o2[d] = 0ull;

    int qig = tid >> 3, kjg = tid & 7;
    int qo  = tid & 63, dhg = tid >> 6;
    __syncthreads();

    for (int k0 = 0; k0 < TT; k0 += 64) {
#pragma unroll
        for (int j = 0; j < 2; j++) {
            int f = tid + j*256;
            int dhi = f >> 4, t4 = f & 15;
            *(float4*)&Ks[dhi][t4*4] = *(const float4*)(Kg + (size_t)dhi*TT + k0 + t4*4);
            float4 v = *(const float4*)(Vg + (size_t)dhi*TT + k0 + t4*4);
            Vs[t4*4+0][dhi] = v.x; Vs[t4*4+1][dhi] = v.y;
            Vs[t4*4+2][dhi] = v.z; Vs[t4*4+3][dhi] = v.w;
        }
        __syncthreads();

        // S = (Q/sqrt(dh))^T K   (pairs along kj)
        u64 s2[2][4];
#pragma unroll
        for (int i = 0; i < 2; i++)
#pragma unroll
            for (int j = 0; j < 4; j++) s2[i][j] = 0ull;
#pragma unroll 8
        for (int dhi = 0; dhi < 32; dhi++) {
            u64 qa = dup2(Qs[dhi][qig*2+0]);
            u64 qb = dup2(Qs[dhi][qig*2+1]);
            const u64* kp = as_u64(&Ks[dhi][kjg*8]);
            u64 k0v = kp[0], k1v = kp[1], k2v = kp[2], k3v = kp[3];
            fma2(s2[0][0], qa, k0v); fma2(s2[0][1], qa, k1v);
            fma2(s2[0][2], qa, k2v); fma2(s2[0][3], qa, k3v);
            fma2(s2[1][0], qb, k0v); fma2(s2[1][1], qb, k1v);
            fma2(s2[1][2], qb, k2v); fma2(s2[1][3], qb, k3v);
        }

        float mnew[2], alp[2], csum[2];
#pragma unroll
        for (int i = 0; i < 2; i++) {
            float s[8];
#pragma unroll
            for (int j = 0; j < 4; j++) {
                float2 f = up2(s2[i][j]); s[j*2] = f.x; s[j*2+1] = f.y;
            }
            float m = s[0];
#pragma unroll
            for (int j = 1; j < 8; j++) m = fmaxf(m, s[j]);
            m = fmaxf(m, __shfl_xor_sync(0xffffffffu, m, 4));
            m = fmaxf(m, __shfl_xor_sync(0xffffffffu, m, 2));
            m = fmaxf(m, __shfl_xor_sync(0xffffffffu, m, 1));
            int qi = qig*2 + i;
            float mold = m_s[qi];
            mnew[i] = fmaxf(mold, m);
            alp[i]  = __expf(mold - mnew[i]);
            float cs = 0.f;
#pragma unroll
            for (int j = 0; j < 8; j++) {
                float p = __expf(s[j] - mnew[i]);
                Ps[qi][kjg*8+j] = p;
                cs += p;
            }
            cs += __shfl_xor_sync(0xffffffffu, cs, 4);
            cs += __shfl_xor_sync(0xffffffffu, cs, 2);
            cs += __shfl_xor_sync(0xffffffffu, cs, 1);
            csum[i] = cs;
        }
        if (kjg == 0) {
#pragma unroll
            for (int i = 0; i < 2; i++) {
                int qi = qig*2 + i;
                m_s[qi]  = mnew[i];
                l_s[qi]  = l_s[qi]*alp[i] + csum[i];
                al_s[qi] = alp[i];
            }
        }
        __syncthreads();

        // O = alpha*O + P V   (pairs along dhi)
        u64 al2 = dup2(al_s[qo]);
#pragma unroll
        for (int d = 0; d < 4; d++) mul2(o2[d], al2);
#pragma unroll 4
        for (int kj = 0; kj < 64; kj++) {
            u64 p2 = dup2(Ps[qo][kj]);
            const u64* vp = as_u64(&Vs[kj][dhg*8]);
            fma2(o2[0], p2, vp[0]); fma2(o2[1], p2, vp[1]);
            fma2(o2[2], p2, vp[2]); fma2(o2[3], p2, vp[3]);
        }
        __syncthreads();
    }

    float linv = 1.f / l_s[qo];
    float* Og = g_attn + (size_t)bh*DHEAD*TT;
#pragma unroll
    for (int d = 0; d < 4; d++) {
        float2 f = up2(o2[d]);
        Og[(size_t)(dhg*8+d*2+0)*TT + q0 + qo] = f.x*linv;
        Og[(size_t)(dhg*8+d*2+1)*TT + q0 + qo] = f.y*linv;
    }
}

// =====================================================================
// Kernel 4: output projection, scaled by tanh(gamma)   (f32x2 n-pairs)
// =====================================================================
__global__ __launch_bounds__(256) void k_proj(
    const float* __restrict__ wo, const float* __restrict__ gamma)
{
    __shared__ float As[32][64];
    __shared__ float Bs[32][64];
    int tid = threadIdx.x;
    int t0 = blockIdx.x*64, d0 = blockIdx.y*64, b = blockIdx.z;
    int ng = tid & 15, mg = tid >> 4;

    u64 acc[4][2];
#pragma unroll
    for (int i = 0; i < 4; i++) { acc[i][0] = 0ull; acc[i][1] = 0ull; }

    for (int c0 = 0; c0 < CC; c0 += 32) {
#pragma unroll
        for (int j = 0; j < 2; j++) {
            int f = tid + j*256;
            int k = f >> 4, m4 = f & 15;
            int d = c0 + k;
            const float* src = g_attn + (((size_t)b*NHEADS + (d&7))*DHEAD + (d>>3))*TT + t0 + m4*4;
            *(float4*)&As[k][m4*4] = *(const float4*)src;
            *(float4*)&Bs[k][m4*4] = *(const float4*)(wo + (size_t)d*CC + d0 + m4*4);
        }
        __syncthreads();
#pragma unroll 8
        for (int k = 0; k < 32; k++) {
            float4 a = *(const float4*)&As[k][mg*4];
            u64 am[4] = {dup2(a.x), dup2(a.y), dup2(a.z), dup2(a.w)};
            u64 b0 = as_u64(&Bs[k][ng*4])[0], b1 = as_u64(&Bs[k][ng*4])[1];
#pragma unroll
            for (int mm = 0; mm < 4; mm++) {
                fma2(acc[mm][0], am[mm], b0);
                fma2(acc[mm][1], am[mm], b1);
            }
        }
        __syncthreads();
    }

    float tg = tanhf(gamma[0]);
#pragma unroll
    for (int np = 0; np < 2; np++) {
        float2 f0 = up2(acc[0][np]), f1 = up2(acc[1][np]);
        float2 f2 = up2(acc[2][np]), f3 = up2(acc[3][np]);
        {
            int d = d0 + ng*4 + np*2;
            size_t base = ((size_t)b*CC + d)*TT + t0 + mg*4;
            *(float4*)&g_proj[base] = make_float4(f0.x*tg, f1.x*tg, f2.x*tg, f3.x*tg);
        }
        {
            int d = d0 + ng*4 + np*2 + 1;
            size_t base = ((size_t)b*CC + d)*TT + t0 + mg*4;
            *(float4*)&g_proj[base] = make_float4(f0.y*tg, f1.y*tg, f2.y*tg, f3.y*tg);
        }
    }
}

// =====================================================================
// Kernel 5: conv3x3 (pad 1) + bias + unpool-add, f32x2.
// Block: 32 oc x (4 rows x 64 cols); grid (16 rowT, 8 ocT, 16 b).
// px-pairs; W staged duplicated (w,w) -> broadcast LDS.64, no dup movs.
// =====================================================================
__global__ __launch_bounds__(256) void k_conv3_unpool(
    const float* __restrict__ x, const float* __restrict__ cw,
    const float* __restrict__ cb, float* __restrict__ out)
{
    __shared__ float  Xs[8][6][68];   // ic x (4+2 halo rows) x (64+2 halo, padded)
    __shared__ float2 Wd[32][72];     // oc x (8 ic * 9 taps), duplicated
    int tid = threadIdx.x;
    int rowT = blockIdx.x, ocT = blockIdx.y, b = blockIdx.z;
    int oc0 = ocT*32;
    int ocg = tid >> 5;              // warp id (warp-uniform) -> 4 oc each
    int pxg = tid & 31;
    int row  = pxg >> 3;             // 0..3
    int colb = (pxg & 7) * 8;        // 0..56

    u64 acc[4][4];
#pragma unroll
    for (int i = 0; i < 4; i++)
#pragma unroll
        for (int j = 0; j < 4; j++) acc[i][j] = 0ull;

    for (int ic0 = 0; ic0 < CC; ic0 += 8) {
        for (int ic = 0; ic < 8; ic++) {
            const float* xc = x + ((size_t)b*CC + ic0 + ic)*PP;
            for (int idx = tid; idx < 6*66; idx += 256) {
                int rr = idx / 66, ccj = idx - rr*66;
                int gr = rowT*4 - 1 + rr, gc = ccj - 1;
                float v = 0.f;
                if ((unsigned)gr < 64u && (unsigned)gc < 64u)
                    v = xc[gr*64 + gc];
                Xs[ic][rr][ccj] = v;
            }
        }
        for (int f = tid; f < 32*72; f += 256) {
            int oc = f / 72, r = f - oc*72;
            float v = cw[(size_t)(oc0+oc)*2304 + (size_t)ic0*9 + r];
            Wd[oc][r] = make_float2(v, v);
        }
        __syncthreads();
#pragma unroll 1
        for (int ic = 0; ic < 8; ic++) {
#pragma unroll
            for (int kh = 0; kh < 3; kh++) {
                float xr[10];
#pragma unroll
                for (int t = 0; t < 10; t++) xr[t] = Xs[ic][row+kh][colb + t];
                u64 pr[9];
#pragma unroll
                for (int t = 0; t < 9; t++) pr[t] = pk2(xr[t], xr[t+1]);
#pragma unroll
                for (int kw = 0; kw < 3; kw++) {
                    int r = ic*9 + kh*3 + kw;
                    u64 w0 = *(const u64*)&Wd[ocg*4+0][r];   // broadcast
                    u64 w1 = *(const u64*)&Wd[ocg*4+1][r];
                    u64 w2 = *(const u64*)&Wd[ocg*4+2][r];
                    u64 w3 = *(const u64*)&Wd[ocg*4+3][r];
#pragma unroll
                    for (int j = 0; j < 4; j++) {
                        u64 xp = pr[kw + 2*j];
                        fma2(acc[0][j], w0, xp);
                        fma2(acc[1][j], w1, xp);
                        fma2(acc[2][j], w2, xp);
                        fma2(acc[3][j], w3, xp);
                    }
                }
            }
        }
        __syncthreads();
    }

    int row_g = rowT*4 + row;
    int h2 = row_g >> 1;
    int subr = (row_g & 1) << 1;
#pragma unroll
    for (int i = 0; i < 4; i++) {
        int oc = oc0 + ocg*4 + i;
        float bias = cb[oc];
        size_t chan = (size_t)b*CC + oc;
        const unsigned char* idxp = g_idx  + chan*TT + (size_t)h2*32;
        const float*        projp = g_proj + chan*TT + (size_t)h2*32;
        float vout[8];
#pragma unroll
        for (int j = 0; j < 4; j++) {
            float2 f = up2(acc[i][j]);
            vout[j*2] = f.x; vout[j*2+1] = f.y;
        }
#pragma unroll
        for (int j = 0; j < 8; j++) {
            int wg = colb + j;
            float v = vout[j] + bias;
            int w2 = wg >> 1;
            if (idxp[w2] == (unsigned char)(subr | (wg & 1)))
                v += projp[w2];
            vout[j] = v;
        }
        float* op = out + chan*PP + (size_t)row_g*64 + colb;
        *(float4*)&op[0] = make_float4(vout[0], vout[1], vout[2], vout[3]);
        *(float4*)&op[4] = make_float4(vout[4], vout[5], vout[6], vout[7]);
    }
}

// =====================================================================
extern "C" void kernel_launch(void* const* d_in, const int* in_sizes, int n_in,
                              void* d_out, int out_size)
{
    const float* x      = (const float*)d_in[0];
    const float* conv_w = (const float*)d_in[1];
    const float* conv_b = (const float*)d_in[2];
    const float* fr_w   = (const float*)d_in[3];
    const float* fr_b   = (const float*)d_in[4];
    const float* wq     = (const float*)d_in[5];
    const float* wk     = (const float*)d_in[6];
    const float* wv     = (const float*)d_in[7];
    const float* wo     = (const float*)d_in[8];
    const float* gamma  = (const float*)d_in[9];
    float* out = (float*)d_out;

    k_fr_pool      <<<dim3(32, 4, BB),        256>>>(x, fr_w, fr_b);
    k_qkv          <<<dim3(16, 4, BB),        256>>>(wq, wk, wv);
    k_attn         <<<dim3(16, BB*NHEADS, 1), 256>>>();
    k_proj         <<<dim3(16, 4, BB),        256>>>(wo, gamma);
    k_conv3_unpool <<<dim3(16, 8, BB),        256>>>(x, conv_w, conv_b, out);
}

// round 7
// speedup vs baseline: 1.2927x; 1.0000x over previous
#include <cuda_runtime.h>
#include <math.h>
#include <stdint.h>

#define BB     16
#define CC     256
#define HH     64
#define WWID   64
#define PP     4096   // HH*WWID
#define TT     1024   // 32*32 pooled tokens
#define NHEADS 8
#define DHEAD  32

typedef unsigned long long u64;

// ---------------- packed fp32 helpers (sm_100 base ISA) ----------------
__device__ __forceinline__ u64 pk2(float lo, float hi) {
    u64 r; asm("mov.b64 %0, {%1,%2};" : "=l"(r) : "f"(lo), "f"(hi)); return r;
}
__device__ __forceinline__ u64 dup2(float v) { return pk2(v, v); }
__device__ __forceinline__ void fma2(u64& acc, u64 a, u64 b) {
    asm("fma.rn.f32x2 %0, %1, %2, %0;" : "+l"(acc) : "l"(a), "l"(b));
}
__device__ __forceinline__ void mul2(u64& acc, u64 a) {
    asm("mul.rn.f32x2 %0, %0, %1;" : "+l"(acc) : "l"(a));
}
__device__ __forceinline__ float2 up2(u64 v) {
    float2 f; asm("mov.b64 {%0,%1}, %2;" : "=f"(f.x), "=f"(f.y) : "l"(v)); return f;
}
__device__ __forceinline__ const u64* as_u64(const float* p) { return (const u64*)p; }

// ---------------- scratch (device globals; no allocs allowed) ----------------
__device__ float         g_pooled[BB*CC*TT];           // [b][c][t]
__device__ unsigned char g_idx   [BB*CC*TT];           // argmax 0..3
__device__ float         g_q   [BB*NHEADS*DHEAD*TT];   // [bh][dhi][t]
__device__ float         g_k   [BB*NHEADS*DHEAD*TT];
__device__ float         g_v   [BB*NHEADS*DHEAD*TT];
__device__ float         g_attn[BB*NHEADS*DHEAD*TT];   // [bh][dhi][t]
__device__ float         g_proj[BB*CC*TT];             // [b][c][t], pre-scaled by tanh(gamma)

// =====================================================================
// Kernel 1: 1x1 conv (feature reduce) + bias + 2x2 maxpool with indices
// f32x2: acc pairs along px; W staged duplicated (w,w) -> broadcast LDS.64
// =====================================================================
__global__ __launch_bounds__(256) void k_fr_pool(
    const float* __restrict__ x, const float* __restrict__ frw,
    const float* __restrict__ frb)
{
    __shared__ float  Xs[32][128];
    __shared__ float2 Wd[64][32];
    int tid = threadIdx.x;
    int hp = blockIdx.x, ocT = blockIdx.y, b = blockIdx.z;
    int oc0 = ocT * 64;
    int ocg = tid >> 5;       // warp id 0..7 -> 8 oc each (warp-uniform)
    int pxg = tid & 31;       // 4 px each

    u64 acc[8][2];
#pragma unroll
    for (int i = 0; i < 8; i++) { acc[i][0] = 0ull; acc[i][1] = 0ull; }

    const float* xb = x + (size_t)b*CC*PP + hp*128;

    for (int c0 = 0; c0 < CC; c0 += 32) {
#pragma unroll
        for (int j = 0; j < 4; j++) {
            int f = tid + j*256;
            int k = f >> 5, c4 = f & 31;
            *(float4*)&Xs[k][c4*4] = *(const float4*)(xb + (size_t)(c0+k)*PP + c4*4);
        }
#pragma unroll
        for (int j = 0; j < 8; j++) {
            int f = tid + j*256;
            int oc = f >> 5, k = f & 31;
            float v = frw[(size_t)(oc0+oc)*CC + c0 + k];
            Wd[oc][k] = make_float2(v, v);
        }
        __syncthreads();
#pragma unroll 8
        for (int k = 0; k < 32; k++) {
            u64 xa = as_u64(&Xs[k][pxg*4])[0];
            u64 xb2 = as_u64(&Xs[k][pxg*4])[1];
#pragma unroll
            for (int i = 0; i < 8; i++) {
                u64 w = *(const u64*)&Wd[ocg*8+i][k];   // broadcast
                fma2(acc[i][0], w, xa);
                fma2(acc[i][1], w, xb2);
            }
        }
        __syncthreads();
    }

    bool low = (pxg < 16);
#pragma unroll
    for (int i = 0; i < 8; i++) {
        int oc = oc0 + ocg*8 + i;
        float bi = frb[oc];
        float2 lo = up2(acc[i][0]);
        float2 hi = up2(acc[i][1]);
        float a0 = lo.x+bi, a1 = lo.y+bi, a2 = hi.x+bi, a3 = hi.y+bi;
        float p0 = __shfl_xor_sync(0xffffffffu, a0, 16);
        float p1 = __shfl_xor_sync(0xffffffffu, a1, 16);
        float p2 = __shfl_xor_sync(0xffffffffu, a2, 16);
        float p3 = __shfl_xor_sync(0xffffffffu, a3, 16);
        if (low) {
            size_t base = ((size_t)b*CC + oc)*TT + hp*32 + pxg*2;
            {   float best = a0; int am = 0;
                if (a1 > best) { best = a1; am = 1; }
                if (p0 > best) { best = p0; am = 2; }
                if (p1 > best) { best = p1; am = 3; }
                g_pooled[base] = best; g_idx[base] = (unsigned char)am; }
            {   float best = a2; int am = 0;
                if (a3 > best) { best = a3; am = 1; }
                if (p2 > best) { best = p2; am = 2; }
                if (p3 > best) { best = p3; am = 3; }
                g_pooled[base+1] = best; g_idx[base+1] = (unsigned char)am; }
        }
    }
}

// =====================================================================
// Kernel 2: QKV projection (f32x2: n-pairs from B tiles; a dup'd, shared x3)
// =====================================================================
__global__ __launch_bounds__(256) void k_qkv(
    const float* __restrict__ wq, const float* __restrict__ wk,
    const float* __restrict__ wv)
{
    __shared__ float As[32][64];
    __shared__ float Bq[32][64], Bk[32][64], Bv[32][64];
    int tid = threadIdx.x;
    int t0 = blockIdx.x*64, d0 = blockIdx.y*64, b = blockIdx.z;
    int ng = tid & 15, mg = tid >> 4;

    u64 aq[4][2], ak[4][2], av[4][2];
#pragma unroll
    for (int i = 0; i < 4; i++)
#pragma unroll
        for (int j = 0; j < 2; j++) { aq[i][j]=0ull; ak[i][j]=0ull; av[i][j]=0ull; }

    const float* pb = g_pooled + (size_t)b*CC*TT;

    for (int c0 = 0; c0 < CC; c0 += 32) {
#pragma unroll
        for (int j = 0; j < 2; j++) {
            int f = tid + j*256;
            int k = f >> 4, m4 = f & 15;
            *(float4*)&As[k][m4*4] = *(const float4*)(pb + (size_t)(c0+k)*TT + t0 + m4*4);
            *(float4*)&Bq[k][m4*4] = *(const float4*)(wq + (size_t)(c0+k)*CC + d0 + m4*4);
            *(float4*)&Bk[k][m4*4] = *(const float4*)(wk + (size_t)(c0+k)*CC + d0 + m4*4);
            *(float4*)&Bv[k][m4*4] = *(const float4*)(wv + (size_t)(c0+k)*CC + d0 + m4*4);
        }
        __syncthreads();
#pragma unroll 8
        for (int k = 0; k < 32; k++) {
            float4 a = *(const float4*)&As[k][mg*4];
            u64 am[4] = {dup2(a.x), dup2(a.y), dup2(a.z), dup2(a.w)};
            u64 bq0 = as_u64(&Bq[k][ng*4])[0], bq1 = as_u64(&Bq[k][ng*4])[1];
            u64 bk0 = as_u64(&Bk[k][ng*4])[0], bk1 = as_u64(&Bk[k][ng*4])[1];
            u64 bv0 = as_u64(&Bv[k][ng*4])[0], bv1 = as_u64(&Bv[k][ng*4])[1];
#pragma unroll
            for (int mm = 0; mm < 4; mm++) {
                fma2(aq[mm][0], am[mm], bq0); fma2(aq[mm][1], am[mm], bq1);
                fma2(ak[mm][0], am[mm], bk0); fma2(ak[mm][1], am[mm], bk1);
                fma2(av[mm][0], am[mm], bv0); fma2(av[mm][1], am[mm], bv1);
            }
        }
        __syncthreads();
    }

#pragma unroll
    for (int np = 0; np < 2; np++) {
        float2 q_[4], k_[4], v_[4];
#pragma unroll
        for (int mm = 0; mm < 4; mm++) {
            q_[mm] = up2(aq[mm][np]); k_[mm] = up2(ak[mm][np]); v_[mm] = up2(av[mm][np]);
        }
#pragma unroll
        for (int sub = 0; sub < 2; sub++) {
            int d = d0 + ng*4 + np*2 + sub;
            int head = d & 7, dhi = d >> 3;
            size_t base = (((size_t)b*NHEADS + head)*DHEAD + dhi)*TT + t0 + mg*4;
            if (sub == 0) {
                *(float4*)&g_q[base] = make_float4(q_[0].x, q_[1].x, q_[2].x, q_[3].x);
                *(float4*)&g_k[base] = make_float4(k_[0].x, k_[1].x, k_[2].x, k_[3].x);
                *(float4*)&g_v[base] = make_float4(v_[0].x, v_[1].x, v_[2].x, v_[3].x);
            } else {
                *(float4*)&g_q[base] = make_float4(q_[0].y, q_[1].y, q_[2].y, q_[3].y);
                *(float4*)&g_k[base] = make_float4(k_[0].y, k_[1].y, k_[2].y, k_[3].y);
                *(float4*)&g_v[base] = make_float4(v_[0].y, v_[1].y, v_[2].y, v_[3].y);
            }
        }
    }
}

// =====================================================================
// Kernel 3: flash attention (f32x2 in S and O loops)
// =====================================================================
__global__ __launch_bounds__(256) void k_attn()
{
    __shared__ float Qs[32][64];
    __shared__ float Ks[32][64];
    __shared__ float Vs[64][36];
    __shared__ float Ps[64][65];
    __shared__ float m_s[64], l_s[64], al_s[64];

    int tid = threadIdx.x;
    int q0 = blockIdx.x*64; int bh = blockIdx.y;
    const float* Qg = g_q + (size_t)bh*DHEAD*TT;
    const float* Kg = g_k + (size_t)bh*DHEAD*TT;
    const float* Vg = g_v + (size_t)bh*DHEAD*TT;
    const float qscale = 0.17677669529663687f;

#pragma unroll
    for (int j = 0; j < 2; j++) {
        int f = tid + j*256;
        int dhi = f >> 4, t4 = f & 15;
        float4 v = *(const float4*)(Qg + (size_t)dhi*TT + q0 + t4*4);
        v.x *= qscale; v.y *= qscale; v.z *= qscale; v.w *= qscale;
        *(float4*)&Qs[dhi][t4*4] = v;
    }
    if (tid < 64) { m_s[tid] = -3.0e38f; l_s[tid] = 0.f; }

    u64 o2[4];
#pragma unroll
    for (int d = 0; d < 4; d++) o2[d] = 0ull;

    int qig = tid >> 3, kjg = tid & 7;
    int qo  = tid & 63, dhg = tid >> 6;
    __syncthreads();

    for (int k0 = 0; k0 < TT; k0 += 64) {
#pragma unroll
        for (int j = 0; j < 2; j++) {
            int f = tid + j*256;
            int dhi = f >> 4, t4 = f & 15;
            *(float4*)&Ks[dhi][t4*4] = *(const float4*)(Kg + (size_t)dhi*TT + k0 + t4*4);
            float4 v = *(const float4*)(Vg + (size_t)dhi*TT + k0 + t4*4);
            Vs[t4*4+0][dhi] = v.x; Vs[t4*4+1][dhi] = v.y;
            Vs[t4*4+2][dhi] = v.z; Vs[t4*4+3][dhi] = v.w;
        }
        __syncthreads();

        // S = (Q/sqrt(dh))^T K   (pairs along kj)
        u64 s2[2][4];
#pragma unroll
        for (int i = 0; i < 2; i++)
#pragma unroll
            for (int j = 0; j < 4; j++) s2[i][j] = 0ull;
#pragma unroll 8
        for (int dhi = 0; dhi < 32; dhi++) {
            u64 qa = dup2(Qs[dhi][qig*2+0]);
            u64 qb = dup2(Qs[dhi][qig*2+1]);
            const u64* kp = as_u64(&Ks[dhi][kjg*8]);
            u64 k0v = kp[0], k1v = kp[1], k2v = kp[2], k3v = kp[3];
            fma2(s2[0][0], qa, k0v); fma2(s2[0][1], qa, k1v);
            fma2(s2[0][2], qa, k2v); fma2(s2[0][3], qa, k3v);
            fma2(s2[1][0], qb, k0v); fma2(s2[1][1], qb, k1v);
            fma2(s2[1][2], qb, k2v); fma2(s2[1][3], qb, k3v);
        }

        float mnew[2], alp[2], csum[2];
#pragma unroll
        for (int i = 0; i < 2; i++) {
            float s[8];
#pragma unroll
            for (int j = 0; j < 4; j++) {
                float2 f = up2(s2[i][j]); s[j*2] = f.x; s[j*2+1] = f.y;
            }
            float m = s[0];
#pragma unroll
            for (int j = 1; j < 8; j++) m = fmaxf(m, s[j]);
            m = fmaxf(m, __shfl_xor_sync(0xffffffffu, m, 4));
            m = fmaxf(m, __shfl_xor_sync(0xffffffffu, m, 2));
            m = fmaxf(m, __shfl_xor_sync(0xffffffffu, m, 1));
            int qi = qig*2 + i;
            float mold = m_s[qi];
            mnew[i] = fmaxf(mold, m);
            alp[i]  = __expf(mold - mnew[i]);
            float cs = 0.f;
#pragma unroll
            for (int j = 0; j < 8; j++) {
                float p = __expf(s[j] - mnew[i]);
                Ps[qi][kjg*8+j] = p;
                cs += p;
            }
            cs += __shfl_xor_sync(0xffffffffu, cs, 4);
            cs += __shfl_xor_sync(0xffffffffu, cs, 2);
            cs += __shfl_xor_sync(0xffffffffu, cs, 1);
            csum[i] = cs;
        }
        if (kjg == 0) {
#pragma unroll
            for (int i = 0; i < 2; i++) {
                int qi = qig*2 + i;
                m_s[qi]  = mnew[i];
                l_s[qi]  = l_s[qi]*alp[i] + csum[i];
                al_s[qi] = alp[i];
            }
        }
        __syncthreads();

        // O = alpha*O + P V   (pairs along dhi)
        u64 al2 = dup2(al_s[qo]);
#pragma unroll
        for (int d = 0; d < 4; d++) mul2(o2[d], al2);
#pragma unroll 4
        for (int kj = 0; kj < 64; kj++) {
            u64 p2 = dup2(Ps[qo][kj]);
            const u64* vp = as_u64(&Vs[kj][dhg*8]);
            fma2(o2[0], p2, vp[0]); fma2(o2[1], p2, vp[1]);
            fma2(o2[2], p2, vp[2]); fma2(o2[3], p2, vp[3]);
        }
        __syncthreads();
    }

    float linv = 1.f / l_s[qo];
    float* Og = g_attn + (size_t)bh*DHEAD*TT;
#pragma unroll
    for (int d = 0; d < 4; d++) {
        float2 f = up2(o2[d]);
        Og[(size_t)(dhg*8+d*2+0)*TT + q0 + qo] = f.x*linv;
        Og[(size_t)(dhg*8+d*2+1)*TT + q0 + qo] = f.y*linv;
    }
}

// =====================================================================
// Kernel 4: output projection, scaled by tanh(gamma)   (f32x2 n-pairs)
// =====================================================================
__global__ __launch_bounds__(256) void k_proj(
    const float* __restrict__ wo, const float* __restrict__ gamma)
{
    __shared__ float As[32][64];
    __shared__ float Bs[32][64];
    int tid = threadIdx.x;
    int t0 = blockIdx.x*64, d0 = blockIdx.y*64, b = blockIdx.z;
    int ng = tid & 15, mg = tid >> 4;

    u64 acc[4][2];
#pragma unroll
    for (int i = 0; i < 4; i++) { acc[i][0] = 0ull; acc[i][1] = 0ull; }

    for (int c0 = 0; c0 < CC; c0 += 32) {
#pragma unroll
        for (int j = 0; j < 2; j++) {
            int f = tid + j*256;
            int k = f >> 4, m4 = f & 15;
            int d = c0 + k;
            const float* src = g_attn + (((size_t)b*NHEADS + (d&7))*DHEAD + (d>>3))*TT + t0 + m4*4;
            *(float4*)&As[k][m4*4] = *(const float4*)src;
            *(float4*)&Bs[k][m4*4] = *(const float4*)(wo + (size_t)d*CC + d0 + m4*4);
        }
        __syncthreads();
#pragma unroll 8
        for (int k = 0; k < 32; k++) {
            float4 a = *(const float4*)&As[k][mg*4];
            u64 am[4] = {dup2(a.x), dup2(a.y), dup2(a.z), dup2(a.w)};
            u64 b0 = as_u64(&Bs[k][ng*4])[0], b1 = as_u64(&Bs[k][ng*4])[1];
#pragma unroll
            for (int mm = 0; mm < 4; mm++) {
                fma2(acc[mm][0], am[mm], b0);
                fma2(acc[mm][1], am[mm], b1);
            }
        }
        __syncthreads();
    }

    float tg = tanhf(gamma[0]);
#pragma unroll
    for (int np = 0; np < 2; np++) {
        float2 f0 = up2(acc[0][np]), f1 = up2(acc[1][np]);
        float2 f2 = up2(acc[2][np]), f3 = up2(acc[3][np]);
        {
            int d = d0 + ng*4 + np*2;
            size_t base = ((size_t)b*CC + d)*TT + t0 + mg*4;
            *(float4*)&g_proj[base] = make_float4(f0.x*tg, f1.x*tg, f2.x*tg, f3.x*tg);
        }
        {
            int d = d0 + ng*4 + np*2 + 1;
            size_t base = ((size_t)b*CC + d)*TT + t0 + mg*4;
            *(float4*)&g_proj[base] = make_float4(f0.y*tg, f1.y*tg, f2.y*tg, f3.y*tg);
        }
    }
}

// =====================================================================
// Kernel 5: conv3x3 (pad 1) + bias + unpool-add, f32x2.
// Block: 32 oc x (4 rows x 64 cols); grid (16 rowT, 8 ocT, 16 b).
// px-pairs; W staged duplicated (w,w) -> broadcast LDS.64, no dup movs.
// =====================================================================
__global__ __launch_bounds__(256) void k_conv3_unpool(
    const float* __restrict__ x, const float* __restrict__ cw,
    const float* __restrict__ cb, float* __restrict__ out)
{
    __shared__ float  Xs[8][6][68];   // ic x (4+2 halo rows) x (64+2 halo, padded)
    __shared__ float2 Wd[32][72];     // oc x (8 ic * 9 taps), duplicated
    int tid = threadIdx.x;
    int rowT = blockIdx.x, ocT = blockIdx.y, b = blockIdx.z;
    int oc0 = ocT*32;
    int ocg = tid >> 5;              // warp id (warp-uniform) -> 4 oc each
    int pxg = tid & 31;
    int row  = pxg >> 3;             // 0..3
    int colb = (pxg & 7) * 8;        // 0..56

    u64 acc[4][4];
#pragma unroll
    for (int i = 0; i < 4; i++)
#pragma unroll
        for (int j = 0; j < 4; j++) acc[i][j] = 0ull;

    for (int ic0 = 0; ic0 < CC; ic0 += 8) {
        for (int ic = 0; ic < 8; ic++) {
            const float* xc = x + ((size_t)b*CC + ic0 + ic)*PP;
            for (int idx = tid; idx < 6*66; idx += 256) {
                int rr = idx / 66, ccj = idx - rr*66;
                int gr = rowT*4 - 1 + rr, gc = ccj - 1;
                float v = 0.f;
                if ((unsigned)gr < 64u && (unsigned)gc < 64u)
                    v = xc[gr*64 + gc];
                Xs[ic][rr][ccj] = v;
            }
        }
        for (int f = tid; f < 32*72; f += 256) {
            int oc = f / 72, r = f - oc*72;
            float v = cw[(size_t)(oc0+oc)*2304 + (size_t)ic0*9 + r];
            Wd[oc][r] = make_float2(v, v);
        }
        __syncthreads();
#pragma unroll 1
        for (int ic = 0; ic < 8; ic++) {
#pragma unroll
            for (int kh = 0; kh < 3; kh++) {
                float xr[10];
#pragma unroll
                for (int t = 0; t < 10; t++) xr[t] = Xs[ic][row+kh][colb + t];
                u64 pr[9];
#pragma unroll
                for (int t = 0; t < 9; t++) pr[t] = pk2(xr[t], xr[t+1]);
#pragma unroll
                for (int kw = 0; kw < 3; kw++) {
                    int r = ic*9 + kh*3 + kw;
                    u64 w0 = *(const u64*)&Wd[ocg*4+0][r];   // broadcast
                    u64 w1 = *(const u64*)&Wd[ocg*4+1][r];
                    u64 w2 = *(const u64*)&Wd[ocg*4+2][r];
                    u64 w3 = *(const u64*)&Wd[ocg*4+3][r];
#pragma unroll
                    for (int j = 0; j < 4; j++) {
                        u64 xp = pr[kw + 2*j];
                        fma2(acc[0][j], w0, xp);
                        fma2(acc[1][j], w1, xp);
                        fma2(acc[2][j], w2, xp);
                        fma2(acc[3][j], w3, xp);
                    }
                }
            }
        }
        __syncthreads();
    }

    int row_g = rowT*4 + row;
    int h2 = row_g >> 1;
    int subr = (row_g & 1) << 1;
#pragma unroll
    for (int i = 0; i < 4; i++) {
        int oc = oc0 + ocg*4 + i;
        float bias = cb[oc];
        size_t chan = (size_t)b*CC + oc;
        const unsigned char* idxp = g_idx  + chan*TT + (size_t)h2*32;
        const float*        projp = g_proj + chan*TT + (size_t)h2*32;
        float vout[8];
#pragma unroll
        for (int j = 0; j < 4; j++) {
            float2 f = up2(acc[i][j]);
            vout[j*2] = f.x; vout[j*2+1] = f.y;
        }
#pragma unroll
        for (int j = 0; j < 8; j++) {
            int wg = colb + j;
            float v = vout[j] + bias;
            int w2 = wg >> 1;
            if (idxp[w2] == (unsigned char)(subr | (wg & 1)))
                v += projp[w2];
            vout[j] = v;
        }
        float* op = out + chan*PP + (size_t)row_g*64 + colb;
        *(float4*)&op[0] = make_float4(vout[0], vout[1], vout[2], vout[3]);
        *(float4*)&op[4] = make_float4(vout[4], vout[5], vout[6], vout[7]);
    }
}

// =====================================================================
extern "C" void kernel_launch(void* const* d_in, const int* in_sizes, int n_in,
                              void* d_out, int out_size)
{
    const float* x      = (const float*)d_in[0];
    const float* conv_w = (const float*)d_in[1];
    const float* conv_b = (const float*)d_in[2];
    const float* fr_w   = (const float*)d_in[3];
    const float* fr_b   = (const float*)d_in[4];
    const float* wq     = (const float*)d_in[5];
    const float* wk     = (const float*)d_in[6];
    const float* wv     = (const float*)d_in[7];
    const float* wo     = (const float*)d_in[8];
    const float* gamma  = (const float*)d_in[9];
    float* out = (float*)d_out;

    k_fr_pool      <<<dim3(32, 4, BB),        256>>>(x, fr_w, fr_b);
    k_qkv          <<<dim3(16, 4, BB),        256>>>(wq, wk, wv);
    k_attn         <<<dim3(16, BB*NHEADS, 1), 256>>>();
    k_proj         <<<dim3(16, 4, BB),        256>>>(wo, gamma);
    k_conv3_unpool <<<dim3(16, 8, BB),        256>>>(x, conv_w, conv_b, out);
}

// round 10
// speedup vs baseline: 2.4171x; 1.8699x over previous
#include <cuda_runtime.h>
#include <math.h>
#include <stdint.h>

#define BB     16
#define CC     256
#define HH     64
#define WWID   64
#define PP     4096   // HH*WWID
#define TT     1024   // 32*32 pooled tokens
#define NHEADS 8
#define DHEAD  32
#define NTIL   4096   // 16 b * 256 tiles (16x16 tiles of 4x4 outputs)

// ---------------- scratch (device globals; no allocs allowed) ----------------
__device__ float         g_pooled[BB*CC*TT];           // [b][c][t]
__device__ unsigned char g_idx   [BB*CC*TT];           // argmax 0..3
__device__ float         g_q   [BB*NHEADS*DHEAD*TT];   // [bh][dhi][t]
__device__ float         g_k   [BB*NHEADS*DHEAD*TT];
__device__ float         g_v   [BB*NHEADS*DHEAD*TT];
__device__ float         g_attn[BB*NHEADS*DHEAD*TT];   // [bh][dhi][t]
__device__ float         g_proj[BB*CC*TT];             // [b][c][t], pre-scaled by tanh(gamma)
__device__ float         g_U[36*CC*CC];                // [p][ic][oc]
__device__ float         g_V[36*CC*NTIL];              // [p][ic][tile]
__device__ float         g_M[36*CC*NTIL];              // [p][oc][tile]

// =====================================================================
// Kernel 1: 1x1 conv (feature reduce) + bias + 2x2 maxpool with indices
// =====================================================================
__global__ __launch_bounds__(256) void k_fr_pool(
    const float* __restrict__ x, const float* __restrict__ frw,
    const float* __restrict__ frb)
{
    __shared__ float Xs[32][128];
    __shared__ float Ws[64][32];
    int tid = threadIdx.x;
    int hp = blockIdx.x, ocT = blockIdx.y, b = blockIdx.z;
    int oc0 = ocT * 64;
    int ocg = tid >> 5;
    int pxg = tid & 31;

    float acc[8][4];
#pragma unroll
    for (int i = 0; i < 8; i++)
#pragma unroll
        for (int j = 0; j < 4; j++) acc[i][j] = 0.f;

    const float* xb = x + (size_t)b*CC*PP + hp*128;

    for (int c0 = 0; c0 < CC; c0 += 32) {
#pragma unroll
        for (int j = 0; j < 4; j++) {
            int f = tid + j*256;
            int k = f >> 5, c4 = f & 31;
            *(float4*)&Xs[k][c4*4] = *(const float4*)(xb + (size_t)(c0+k)*PP + c4*4);
        }
#pragma unroll
        for (int j = 0; j < 8; j++) {
            int f = tid + j*256;
            int oc = f >> 5, k = f & 31;
            Ws[oc][k] = frw[(size_t)(oc0+oc)*CC + c0 + k];
        }
        __syncthreads();
#pragma unroll 8
        for (int k = 0; k < 32; k++) {
            float4 xv = *(const float4*)&Xs[k][pxg*4];
#pragma unroll
            for (int i = 0; i < 8; i++) {
                float w = Ws[ocg*8+i][k];
                acc[i][0] = fmaf(w, xv.x, acc[i][0]);
                acc[i][1] = fmaf(w, xv.y, acc[i][1]);
                acc[i][2] = fmaf(w, xv.z, acc[i][2]);
                acc[i][3] = fmaf(w, xv.w, acc[i][3]);
            }
        }
        __syncthreads();
    }

    bool low = (pxg < 16);
#pragma unroll
    for (int i = 0; i < 8; i++) {
        int oc = oc0 + ocg*8 + i;
        float bi = frb[oc];
        float a0 = acc[i][0]+bi, a1 = acc[i][1]+bi;
        float a2 = acc[i][2]+bi, a3 = acc[i][3]+bi;
        float p0 = __shfl_xor_sync(0xffffffffu, a0, 16);
        float p1 = __shfl_xor_sync(0xffffffffu, a1, 16);
        float p2 = __shfl_xor_sync(0xffffffffu, a2, 16);
        float p3 = __shfl_xor_sync(0xffffffffu, a3, 16);
        if (low) {
            size_t base = ((size_t)b*CC + oc)*TT + hp*32 + pxg*2;
            {   float best = a0; int am = 0;
                if (a1 > best) { best = a1; am = 1; }
                if (p0 > best) { best = p0; am = 2; }
                if (p1 > best) { best = p1; am = 3; }
                g_pooled[base] = best; g_idx[base] = (unsigned char)am; }
            {   float best = a2; int am = 0;
                if (a3 > best) { best = a3; am = 1; }
                if (p2 > best) { best = p2; am = 2; }
                if (p3 > best) { best = p3; am = 3; }
                g_pooled[base+1] = best; g_idx[base+1] = (unsigned char)am; }
        }
    }
}

// =====================================================================
// Kernel 2: QKV projection
// =====================================================================
__global__ __launch_bounds__(256) void k_qkv(
    const float* __restrict__ wq, const float* __restrict__ wk,
    const float* __restrict__ wv)
{
    __shared__ float As[32][64];
    __shared__ float Bq[32][64], Bk[32][64], Bv[32][64];
    int tid = threadIdx.x;
    int t0 = blockIdx.x*64, d0 = blockIdx.y*64, b = blockIdx.z;
    int ng = tid & 15, mg = tid >> 4;

    float aq[4][4], ak[4][4], av[4][4];
#pragma unroll
    for (int i = 0; i < 4; i++)
#pragma unroll
        for (int j = 0; j < 4; j++) { aq[i][j]=0.f; ak[i][j]=0.f; av[i][j]=0.f; }

    const float* pb = g_pooled + (size_t)b*CC*TT;

    for (int c0 = 0; c0 < CC; c0 += 32) {
#pragma unroll
        for (int j = 0; j < 2; j++) {
            int f = tid + j*256;
            int k = f >> 4, m4 = f & 15;
            *(float4*)&As[k][m4*4] = *(const float4*)(pb + (size_t)(c0+k)*TT + t0 + m4*4);
            *(float4*)&Bq[k][m4*4] = *(const float4*)(wq + (size_t)(c0+k)*CC + d0 + m4*4);
            *(float4*)&Bk[k][m4*4] = *(const float4*)(wk + (size_t)(c0+k)*CC + d0 + m4*4);
            *(float4*)&Bv[k][m4*4] = *(const float4*)(wv + (size_t)(c0+k)*CC + d0 + m4*4);
        }
        __syncthreads();
#pragma unroll 8
        for (int k = 0; k < 32; k++) {
            float4 a  = *(const float4*)&As[k][mg*4];
            float4 q4 = *(const float4*)&Bq[k][ng*4];
            float4 k4 = *(const float4*)&Bk[k][ng*4];
            float4 v4 = *(const float4*)&Bv[k][ng*4];
            float am[4] = {a.x,a.y,a.z,a.w};
            float qn[4] = {q4.x,q4.y,q4.z,q4.w};
            float kn[4] = {k4.x,k4.y,k4.z,k4.w};
            float vn[4] = {v4.x,v4.y,v4.z,v4.w};
#pragma unroll
            for (int mm = 0; mm < 4; mm++)
#pragma unroll
                for (int nn = 0; nn < 4; nn++) {
                    aq[mm][nn] = fmaf(am[mm], qn[nn], aq[mm][nn]);
                    ak[mm][nn] = fmaf(am[mm], kn[nn], ak[mm][nn]);
                    av[mm][nn] = fmaf(am[mm], vn[nn], av[mm][nn]);
                }
        }
        __syncthreads();
    }

#pragma unroll
    for (int nn = 0; nn < 4; nn++) {
        int d = d0 + ng*4 + nn;
        int head = d & 7, dhi = d >> 3;
        size_t base = (((size_t)b*NHEADS + head)*DHEAD + dhi)*TT + t0 + mg*4;
        *(float4*)&g_q[base] = make_float4(aq[0][nn], aq[1][nn], aq[2][nn], aq[3][nn]);
        *(float4*)&g_k[base] = make_float4(ak[0][nn], ak[1][nn], ak[2][nn], ak[3][nn]);
        *(float4*)&g_v[base] = make_float4(av[0][nn], av[1][nn], av[2][nn], av[3][nn]);
    }
}

// =====================================================================
// Kernel 3: flash attention
// =====================================================================
__global__ __launch_bounds__(256) void k_attn()
{
    __shared__ float Qs[32][64];
    __shared__ float Ks[32][64];
    __shared__ float Vs[64][36];
    __shared__ float Ps[64][65];
    __shared__ float m_s[64], l_s[64], al_s[64];

    int tid = threadIdx.x;
    int q0 = blockIdx.x*64; int bh = blockIdx.y;
    const float* Qg = g_q + (size_t)bh*DHEAD*TT;
    const float* Kg = g_k + (size_t)bh*DHEAD*TT;
    const float* Vg = g_v + (size_t)bh*DHEAD*TT;
    const float qscale = 0.17677669529663687f;

#pragma unroll
    for (int j = 0; j < 2; j++) {
        int f = tid + j*256;
        int dhi = f >> 4, t4 = f & 15;
        float4 v = *(const float4*)(Qg + (size_t)dhi*TT + q0 + t4*4);
        v.x *= qscale; v.y *= qscale; v.z *= qscale; v.w *= qscale;
        *(float4*)&Qs[dhi][t4*4] = v;
    }
    if (tid < 64) { m_s[tid] = -3.0e38f; l_s[tid] = 0.f; }

    float o[8];
#pragma unroll
    for (int d = 0; d < 8; d++) o[d] = 0.f;

    int qig = tid >> 3, kjg = tid & 7;
    int qo  = tid & 63, dhg = tid >> 6;
    __syncthreads();

    for (int k0 = 0; k0 < TT; k0 += 64) {
#pragma unroll
        for (int j = 0; j < 2; j++) {
            int f = tid + j*256;
            int dhi = f >> 4, t4 = f & 15;
            *(float4*)&Ks[dhi][t4*4] = *(const float4*)(Kg + (size_t)dhi*TT + k0 + t4*4);
            float4 v = *(const float4*)(Vg + (size_t)dhi*TT + k0 + t4*4);
            Vs[t4*4+0][dhi] = v.x; Vs[t4*4+1][dhi] = v.y;
            Vs[t4*4+2][dhi] = v.z; Vs[t4*4+3][dhi] = v.w;
        }
        __syncthreads();

        float s[2][8];
#pragma unroll
        for (int i = 0; i < 2; i++)
#pragma unroll
            for (int j = 0; j < 8; j++) s[i][j] = 0.f;
#pragma unroll 8
        for (int dhi = 0; dhi < 32; dhi++) {
            float q0v = Qs[dhi][qig*2+0];
            float q1v = Qs[dhi][qig*2+1];
            float4 ka = *(const float4*)&Ks[dhi][kjg*8];
            float4 kb = *(const float4*)&Ks[dhi][kjg*8+4];
            float kv[8] = {ka.x,ka.y,ka.z,ka.w,kb.x,kb.y,kb.z,kb.w};
#pragma unroll
            for (int j = 0; j < 8; j++) {
                s[0][j] = fmaf(q0v, kv[j], s[0][j]);
                s[1][j] = fmaf(q1v, kv[j], s[1][j]);
            }
        }

        float mnew[2], alp[2], csum[2];
#pragma unroll
        for (int i = 0; i < 2; i++) {
            float m = s[i][0];
#pragma unroll
            for (int j = 1; j < 8; j++) m = fmaxf(m, s[i][j]);
            m = fmaxf(m, __shfl_xor_sync(0xffffffffu, m, 4));
            m = fmaxf(m, __shfl_xor_sync(0xffffffffu, m, 2));
            m = fmaxf(m, __shfl_xor_sync(0xffffffffu, m, 1));
            int qi = qig*2 + i;
            float mold = m_s[qi];
            mnew[i] = fmaxf(mold, m);
            alp[i]  = __expf(mold - mnew[i]);
            float cs = 0.f;
#pragma unroll
            for (int j = 0; j < 8; j++) {
                float p = __expf(s[i][j] - mnew[i]);
                Ps[qi][kjg*8+j] = p;
                cs += p;
            }
            cs += __shfl_xor_sync(0xffffffffu, cs, 4);
            cs += __shfl_xor_sync(0xffffffffu, cs, 2);
            cs += __shfl_xor_sync(0xffffffffu, cs, 1);
            csum[i] = cs;
        }
        if (kjg == 0) {
#pragma unroll
            for (int i = 0; i < 2; i++) {
                int qi = qig*2 + i;
                m_s[qi]  = mnew[i];
                l_s[qi]  = l_s[qi]*alp[i] + csum[i];
                al_s[qi] = alp[i];
            }
        }
        __syncthreads();

        float alpha = al_s[qo];
#pragma unroll
        for (int d = 0; d < 8; d++) o[d] *= alpha;
#pragma unroll 4
        for (int kj = 0; kj < 64; kj++) {
            float p = Ps[qo][kj];
            float4 va = *(const float4*)&Vs[kj][dhg*8];
            float4 vb = *(const float4*)&Vs[kj][dhg*8+4];
            o[0] = fmaf(p, va.x, o[0]); o[1] = fmaf(p, va.y, o[1]);
            o[2] = fmaf(p, va.z, o[2]); o[3] = fmaf(p, va.w, o[3]);
            o[4] = fmaf(p, vb.x, o[4]); o[5] = fmaf(p, vb.y, o[5]);
            o[6] = fmaf(p, vb.z, o[6]); o[7] = fmaf(p, vb.w, o[7]);
        }
        __syncthreads();
    }

    float linv = 1.f / l_s[qo];
    float* Og = g_attn + (size_t)bh*DHEAD*TT;
#pragma unroll
    for (int d = 0; d < 8; d++)
        Og[(size_t)(dhg*8+d)*TT + q0 + qo] = o[d]*linv;
}

// =====================================================================
// Kernel 4: output projection, scaled by tanh(gamma)
// =====================================================================
__global__ __launch_bounds__(256) void k_proj(
    const float* __restrict__ wo, const float* __restrict__ gamma)
{
    __shared__ float As[32][64];
    __shared__ float Bs[32][64];
    int tid = threadIdx.x;
    int t0 = blockIdx.x*64, d0 = blockIdx.y*64, b = blockIdx.z;
    int ng = tid & 15, mg = tid >> 4;

    float acc[4][4];
#pragma unroll
    for (int i = 0; i < 4; i++)
#pragma unroll
        for (int j = 0; j < 4; j++) acc[i][j] = 0.f;

    for (int c0 = 0; c0 < CC; c0 += 32) {
#pragma unroll
        for (int j = 0; j < 2; j++) {
            int f = tid + j*256;
            int k = f >> 4, m4 = f & 15;
            int d = c0 + k;
            const float* src = g_attn + (((size_t)b*NHEADS + (d&7))*DHEAD + (d>>3))*TT + t0 + m4*4;
            *(float4*)&As[k][m4*4] = *(const float4*)src;
            *(float4*)&Bs[k][m4*4] = *(const float4*)(wo + (size_t)d*CC + d0 + m4*4);
        }
        __syncthreads();
#pragma unroll 8
        for (int k = 0; k < 32; k++) {
            float4 a  = *(const float4*)&As[k][mg*4];
            float4 bv = *(const float4*)&Bs[k][ng*4];
            float am[4] = {a.x,a.y,a.z,a.w};
            float bn[4] = {bv.x,bv.y,bv.z,bv.w};
#pragma unroll
            for (int mm = 0; mm < 4; mm++)
#pragma unroll
                for (int nn = 0; nn < 4; nn++)
                    acc[mm][nn] = fmaf(am[mm], bn[nn], acc[mm][nn]);
        }
        __syncthreads();
    }

    float tg = tanhf(gamma[0]);
#pragma unroll
    for (int nn = 0; nn < 4; nn++) {
        int d = d0 + ng*4 + nn;
        size_t base = ((size_t)b*CC + d)*TT + t0 + mg*4;
        *(float4*)&g_proj[base] =
            make_float4(acc[0][nn]*tg, acc[1][nn]*tg, acc[2][nn]*tg, acc[3][nn]*tg);
    }
}

// =====================================================================
// Winograd F(4x4, 3x3)
// =====================================================================

// ---- W1: weight transform  U = G g G^T  -> g_U[p][ic][oc]
__device__ __forceinline__ void gfilt(const float a, const float b, const float c,
                                      float* o) {
    o[0] = 0.25f*a;
    o[1] = (-a - b - c) * (1.f/6.f);
    o[2] = (-a + b - c) * (1.f/6.f);
    o[3] = a*(1.f/24.f) + b*(1.f/12.f) + c*(1.f/6.f);
    o[4] = a*(1.f/24.f) - b*(1.f/12.f) + c*(1.f/6.f);
    o[5] = c;
}

__global__ __launch_bounds__(256) void k_wg_wt(const float* __restrict__ cw)
{
    int idx = blockIdx.x*256 + threadIdx.x;   // 0..65535
    int oc = idx & 255, ic = idx >> 8;
    const float* g = cw + (size_t)oc*2304 + ic*9;
    float g00=g[0],g01=g[1],g02=g[2],g10=g[3],g11=g[4],g12=g[5],g20=g[6],g21=g[7],g22=g[8];

    float t[6][3];
    {   // columns: T = G g (6x3)
        float o0[6], o1[6], o2[6];
        gfilt(g00, g10, g20, o0);
        gfilt(g01, g11, g21, o1);
        gfilt(g02, g12, g22, o2);
#pragma unroll
        for (int r = 0; r < 6; r++) { t[r][0]=o0[r]; t[r][1]=o1[r]; t[r][2]=o2[r]; }
    }
#pragma unroll
    for (int r = 0; r < 6; r++) {
        float o[6];
        gfilt(t[r][0], t[r][1], t[r][2], o);
#pragma unroll
        for (int c = 0; c < 6; c++)
            g_U[(size_t)(r*6+c)*CC*CC + (size_t)ic*CC + oc] = o[c];
    }
}

// ---- W2: input transform  V = B^T d B  -> g_V[p][ic][tile]
__device__ __forceinline__ void btrans(const float* d, float* o) {
    // d[0..5] one line; B^T applied
    o[0] = 4.f*d[0] - 5.f*d[2] + d[4];
    o[1] = -4.f*d[1] - 4.f*d[2] + d[3] + d[4];
    o[2] =  4.f*d[1] - 4.f*d[2] - d[3] + d[4];
    o[3] = -2.f*d[1] -     d[2] + 2.f*d[3] + d[4];
    o[4] =  2.f*d[1] -     d[2] - 2.f*d[3] + d[4];
    o[5] =  4.f*d[1] - 5.f*d[3] + d[5];
}

__global__ __launch_bounds__(256) void k_wg_in(const float* __restrict__ x)
{
    int tid = threadIdx.x;
    int tx = tid & 15, ic_l = tid >> 4;
    int ty = blockIdx.x, icT = blockIdx.y, b = blockIdx.z;
    int ic = icT*16 + ic_l;
    int tile = b*256 + ty*16 + tx;

    const float* xp = x + ((size_t)b*CC + ic)*PP;
    int gy0 = ty*4 - 1, gx0 = tx*4 - 1;

    float d[6][6];
#pragma unroll
    for (int i = 0; i < 6; i++) {
        int gy = gy0 + i;
        bool yok = (unsigned)gy < 64u;
#pragma unroll
        for (int j = 0; j < 6; j++) {
            int gx = gx0 + j;
            d[i][j] = (yok && (unsigned)gx < 64u) ? xp[gy*64 + gx] : 0.f;
        }
    }
    // columns first: W[r][j] = Bt row r applied to column j
    float wcol[6][6];
#pragma unroll
    for (int j = 0; j < 6; j++) {
        float col[6] = {d[0][j], d[1][j], d[2][j], d[3][j], d[4][j], d[5][j]};
        float o[6];
        btrans(col, o);
#pragma unroll
        for (int r = 0; r < 6; r++) wcol[r][j] = o[r];
    }
#pragma unroll
    for (int r = 0; r < 6; r++) {
        float o[6];
        btrans(wcol[r], o);
#pragma unroll
        for (int c = 0; c < 6; c++)
            g_V[(size_t)(r*6+c)*CC*NTIL + (size_t)ic*NTIL + tile] = o[c];
    }
}

// ---- W3: 36 batched GEMMs  M_p[oc][tile] = sum_ic U_p[ic][oc] * V_p[ic][tile]
__global__ __launch_bounds__(256) void k_wg_gemm()
{
    __shared__ float As[32][64];
    __shared__ float Bs[32][64];
    int tid = threadIdx.x;
    int t0 = blockIdx.x*64, oc0 = blockIdx.y*64, p = blockIdx.z;
    int ng = tid & 15, mg = tid >> 4;

    const float* Vp = g_V + (size_t)p*CC*NTIL;
    const float* Up = g_U + (size_t)p*CC*CC;

    float acc[4][4];
#pragma unroll
    for (int i = 0; i < 4; i++)
#pragma unroll
        for (int j = 0; j < 4; j++) acc[i][j] = 0.f;

    for (int c0 = 0; c0 < CC; c0 += 32) {
#pragma unroll
        for (int j = 0; j < 2; j++) {
            int f = tid + j*256;
            int k = f >> 4, m4 = f & 15;
            *(float4*)&As[k][m4*4] = *(const float4*)(Vp + (size_t)(c0+k)*NTIL + t0 + m4*4);
            *(float4*)&Bs[k][m4*4] = *(const float4*)(Up + (size_t)(c0+k)*CC + oc0 + m4*4);
        }
        __syncthreads();
#pragma unroll 8
        for (int k = 0; k < 32; k++) {
            float4 a  = *(const float4*)&As[k][mg*4];
            float4 bv = *(const float4*)&Bs[k][ng*4];
            float am[4] = {a.x,a.y,a.z,a.w};
            float bn[4] = {bv.x,bv.y,bv.z,bv.w};
#pragma unroll
            for (int mm = 0; mm < 4; mm++)
#pragma unroll
                for (int nn = 0; nn < 4; nn++)
                    acc[mm][nn] = fmaf(am[mm], bn[nn], acc[mm][nn]);
        }
        __syncthreads();
    }

    float* Mp = g_M + (size_t)p*CC*NTIL;
#pragma unroll
    for (int nn = 0; nn < 4; nn++) {
        int oc = oc0 + ng*4 + nn;
        *(float4*)(Mp + (size_t)oc*NTIL + t0 + mg*4) =
            make_float4(acc[0][nn], acc[1][nn], acc[2][nn], acc[3][nn]);
    }
}

// ---- W4: output transform  Y = A^T M A  + bias + unpool-gated add -> out
__device__ __forceinline__ void atrans(const float* w, float* o) {
    o[0] = w[0] + w[1] + w[2] + w[3] + w[4];
    o[1] = w[1] - w[2] + 2.f*w[3] - 2.f*w[4];
    o[2] = w[1] + w[2] + 4.f*w[3] + 4.f*w[4];
    o[3] = w[1] - w[2] + 8.f*w[3] - 8.f*w[4] + w[5];
}

__global__ __launch_bounds__(256) void k_wg_out(
    const float* __restrict__ cb, float* __restrict__ out)
{
    int tid = threadIdx.x;
    int tx = tid & 15, oc_l = tid >> 4;
    int ty = blockIdx.x, ocT = blockIdx.y, b = blockIdx.z;
    int oc = ocT*16 + oc_l;
    int tile = b*256 + ty*16 + tx;

    float m[6][6];
#pragma unroll
    for (int r = 0; r < 6; r++)
#pragma unroll
        for (int c = 0; c < 6; c++)
            m[r][c] = g_M[(size_t)(r*6+c)*CC*NTIL + (size_t)oc*NTIL + tile];

    // columns: Z[i][j] = At row i applied to column j  (4x6)
    float z[4][6];
#pragma unroll
    for (int j = 0; j < 6; j++) {
        float col[6] = {m[0][j], m[1][j], m[2][j], m[3][j], m[4][j], m[5][j]};
        float o[4];
        atrans(col, o);
#pragma unroll
        for (int i = 0; i < 4; i++) z[i][j] = o[i];
    }

    float bias = cb[oc];
    size_t chan = (size_t)b*CC + oc;
    const unsigned char* idxp  = g_idx  + chan*TT;
    const float*         projp = g_proj + chan*TT;
    float* op = out + chan*PP;

#pragma unroll
    for (int r = 0; r < 4; r++) {
        float y[4];
        atrans(z[r], y);
        int gy = ty*4 + r;
        int h2 = gy >> 1;
        int subr = (gy & 1) << 1;
        float v[4];
#pragma unroll
        for (int c = 0; c < 4; c++) {
            int gx = tx*4 + c;
            float vv = y[c] + bias;
            int w2 = gx >> 1;
            if (idxp[h2*32 + w2] == (unsigned char)(subr | (gx & 1)))
                vv += projp[h2*32 + w2];
            v[c] = vv;
        }
        *(float4*)(op + (size_t)gy*64 + tx*4) = make_float4(v[0], v[1], v[2], v[3]);
    }
}

// =====================================================================
extern "C" void kernel_launch(void* const* d_in, const int* in_sizes, int n_in,
                              void* d_out, int out_size)
{
    const float* x      = (const float*)d_in[0];
    const float* conv_w = (const float*)d_in[1];
    const float* conv_b = (const float*)d_in[2];
    const float* fr_w   = (const float*)d_in[3];
    const float* fr_b   = (const float*)d_in[4];
    const float* wq     = (const float*)d_in[5];
    const float* wk     = (const float*)d_in[6];
    const float* wv     = (const float*)d_in[7];
    const float* wo     = (const float*)d_in[8];
    const float* gamma  = (const float*)d_in[9];
    float* out = (float*)d_out;

    k_wg_wt   <<<256, 256>>>(conv_w);
    k_wg_in   <<<dim3(16, 16, BB),       256>>>(x);
    k_fr_pool <<<dim3(32, 4, BB),        256>>>(x, fr_w, fr_b);
    k_wg_gemm <<<dim3(64, 4, 36),        256>>>();
    k_qkv     <<<dim3(16, 4, BB),        256>>>(wq, wk, wv);
    k_attn    <<<dim3(16, BB*NHEADS, 1), 256>>>();
    k_proj    <<<dim3(16, 4, BB),        256>>>(wo, gamma);
    k_wg_out  <<<dim3(16, 16, BB),       256>>>(conv_b, out);
}

// round 11
// speedup vs baseline: 2.4617x; 1.0184x over previous
#include <cuda_runtime.h>
#include <math.h>
#include <stdint.h>

#define BB     16
#define CC     256
#define HH     64
#define WWID   64
#define PP     4096   // HH*WWID
#define TT     1024   // 32*32 pooled tokens
#define NHEADS 8
#define DHEAD  32
#define NTIL   4096   // 16 b * 256 tiles (16x16 tiles of 4x4 outputs)

// ---------------- scratch (device globals; no allocs allowed) ----------------
__device__ float         g_pooled[BB*CC*TT];           // [b][c][t]
__device__ unsigned char g_idx   [BB*CC*TT];           // argmax 0..3
__device__ float         g_q   [BB*NHEADS*DHEAD*TT];   // [bh][dhi][t]
__device__ float         g_k   [BB*NHEADS*DHEAD*TT];
__device__ float         g_v   [BB*NHEADS*DHEAD*TT];
__device__ float         g_attn[BB*NHEADS*DHEAD*TT];   // [bh][dhi][t]
__device__ float         g_proj[BB*CC*TT];             // [b][c][t], pre-scaled by tanh(gamma)
__device__ float         g_U[36*CC*CC];                // [p][ic][oc]
__device__ float         g_V[36*CC*NTIL];              // [p][ic][tile]
__device__ float         g_M[36*CC*NTIL];              // [p][oc][tile]

// =====================================================================
// Kernel 1: 1x1 conv (feature reduce) + bias + 2x2 maxpool with indices
// =====================================================================
__global__ __launch_bounds__(256) void k_fr_pool(
    const float* __restrict__ x, const float* __restrict__ frw,
    const float* __restrict__ frb)
{
    __shared__ float Xs[32][128];
    __shared__ float Ws[64][32];
    int tid = threadIdx.x;
    int hp = blockIdx.x, ocT = blockIdx.y, b = blockIdx.z;
    int oc0 = ocT * 64;
    int ocg = tid >> 5;
    int pxg = tid & 31;

    float acc[8][4];
#pragma unroll
    for (int i = 0; i < 8; i++)
#pragma unroll
        for (int j = 0; j < 4; j++) acc[i][j] = 0.f;

    const float* xb = x + (size_t)b*CC*PP + hp*128;

    for (int c0 = 0; c0 < CC; c0 += 32) {
#pragma unroll
        for (int j = 0; j < 4; j++) {
            int f = tid + j*256;
            int k = f >> 5, c4 = f & 31;
            *(float4*)&Xs[k][c4*4] = *(const float4*)(xb + (size_t)(c0+k)*PP + c4*4);
        }
#pragma unroll
        for (int j = 0; j < 8; j++) {
            int f = tid + j*256;
            int oc = f >> 5, k = f & 31;
            Ws[oc][k] = frw[(size_t)(oc0+oc)*CC + c0 + k];
        }
        __syncthreads();
#pragma unroll 8
        for (int k = 0; k < 32; k++) {
            float4 xv = *(const float4*)&Xs[k][pxg*4];
#pragma unroll
            for (int i = 0; i < 8; i++) {
                float w = Ws[ocg*8+i][k];
                acc[i][0] = fmaf(w, xv.x, acc[i][0]);
                acc[i][1] = fmaf(w, xv.y, acc[i][1]);
                acc[i][2] = fmaf(w, xv.z, acc[i][2]);
                acc[i][3] = fmaf(w, xv.w, acc[i][3]);
            }
        }
        __syncthreads();
    }

    bool low = (pxg < 16);
#pragma unroll
    for (int i = 0; i < 8; i++) {
        int oc = oc0 + ocg*8 + i;
        float bi = frb[oc];
        float a0 = acc[i][0]+bi, a1 = acc[i][1]+bi;
        float a2 = acc[i][2]+bi, a3 = acc[i][3]+bi;
        float p0 = __shfl_xor_sync(0xffffffffu, a0, 16);
        float p1 = __shfl_xor_sync(0xffffffffu, a1, 16);
        float p2 = __shfl_xor_sync(0xffffffffu, a2, 16);
        float p3 = __shfl_xor_sync(0xffffffffu, a3, 16);
        if (low) {
            size_t base = ((size_t)b*CC + oc)*TT + hp*32 + pxg*2;
            {   float best = a0; int am = 0;
                if (a1 > best) { best = a1; am = 1; }
                if (p0 > best) { best = p0; am = 2; }
                if (p1 > best) { best = p1; am = 3; }
                g_pooled[base] = best; g_idx[base] = (unsigned char)am; }
            {   float best = a2; int am = 0;
                if (a3 > best) { best = a3; am = 1; }
                if (p2 > best) { best = p2; am = 2; }
                if (p3 > best) { best = p3; am = 3; }
                g_pooled[base+1] = best; g_idx[base+1] = (unsigned char)am; }
        }
    }
}

// =====================================================================
// Kernel 2: QKV projection
// =====================================================================
__global__ __launch_bounds__(256) void k_qkv(
    const float* __restrict__ wq, const float* __restrict__ wk,
    const float* __restrict__ wv)
{
    __shared__ float As[32][64];
    __shared__ float Bq[32][64], Bk[32][64], Bv[32][64];
    int tid = threadIdx.x;
    int t0 = blockIdx.x*64, d0 = blockIdx.y*64, b = blockIdx.z;
    int ng = tid & 15, mg = tid >> 4;

    float aq[4][4], ak[4][4], av[4][4];
#pragma unroll
    for (int i = 0; i < 4; i++)
#pragma unroll
        for (int j = 0; j < 4; j++) { aq[i][j]=0.f; ak[i][j]=0.f; av[i][j]=0.f; }

    const float* pb = g_pooled + (size_t)b*CC*TT;

    for (int c0 = 0; c0 < CC; c0 += 32) {
#pragma unroll
        for (int j = 0; j < 2; j++) {
            int f = tid + j*256;
            int k = f >> 4, m4 = f & 15;
            *(float4*)&As[k][m4*4] = *(const float4*)(pb + (size_t)(c0+k)*TT + t0 + m4*4);
            *(float4*)&Bq[k][m4*4] = *(const float4*)(wq + (size_t)(c0+k)*CC + d0 + m4*4);
            *(float4*)&Bk[k][m4*4] = *(const float4*)(wk + (size_t)(c0+k)*CC + d0 + m4*4);
            *(float4*)&Bv[k][m4*4] = *(const float4*)(wv + (size_t)(c0+k)*CC + d0 + m4*4);
        }
        __syncthreads();
#pragma unroll 8
        for (int k = 0; k < 32; k++) {
            float4 a  = *(const float4*)&As[k][mg*4];
            float4 q4 = *(const float4*)&Bq[k][ng*4];
            float4 k4 = *(const float4*)&Bk[k][ng*4];
            float4 v4 = *(const float4*)&Bv[k][ng*4];
            float am[4] = {a.x,a.y,a.z,a.w};
            float qn[4] = {q4.x,q4.y,q4.z,q4.w};
            float kn[4] = {k4.x,k4.y,k4.z,k4.w};
            float vn[4] = {v4.x,v4.y,v4.z,v4.w};
#pragma unroll
            for (int mm = 0; mm < 4; mm++)
#pragma unroll
                for (int nn = 0; nn < 4; nn++) {
                    aq[mm][nn] = fmaf(am[mm], qn[nn], aq[mm][nn]);
                    ak[mm][nn] = fmaf(am[mm], kn[nn], ak[mm][nn]);
                    av[mm][nn] = fmaf(am[mm], vn[nn], av[mm][nn]);
                }
        }
        __syncthreads();
    }

#pragma unroll
    for (int nn = 0; nn < 4; nn++) {
        int d = d0 + ng*4 + nn;
        int head = d & 7, dhi = d >> 3;
        size_t base = (((size_t)b*NHEADS + head)*DHEAD + dhi)*TT + t0 + mg*4;
        *(float4*)&g_q[base] = make_float4(aq[0][nn], aq[1][nn], aq[2][nn], aq[3][nn]);
        *(float4*)&g_k[base] = make_float4(ak[0][nn], ak[1][nn], ak[2][nn], ak[3][nn]);
        *(float4*)&g_v[base] = make_float4(av[0][nn], av[1][nn], av[2][nn], av[3][nn]);
    }
}

// =====================================================================
// Kernel 3: flash attention
// =====================================================================
__global__ __launch_bounds__(256) void k_attn()
{
    __shared__ float Qs[32][64];
    __shared__ float Ks[32][64];
    __shared__ float Vs[64][36];
    __shared__ float Ps[64][65];
    __shared__ float m_s[64], l_s[64], al_s[64];

    int tid = threadIdx.x;
    int q0 = blockIdx.x*64; int bh = blockIdx.y;
    const float* Qg = g_q + (size_t)bh*DHEAD*TT;
    const float* Kg = g_k + (size_t)bh*DHEAD*TT;
    const float* Vg = g_v + (size_t)bh*DHEAD*TT;
    const float qscale = 0.17677669529663687f;

#pragma unroll
    for (int j = 0; j < 2; j++) {
        int f = tid + j*256;
        int dhi = f >> 4, t4 = f & 15;
        float4 v = *(const float4*)(Qg + (size_t)dhi*TT + q0 + t4*4);
        v.x *= qscale; v.y *= qscale; v.z *= qscale; v.w *= qscale;
        *(float4*)&Qs[dhi][t4*4] = v;
    }
    if (tid < 64) { m_s[tid] = -3.0e38f; l_s[tid] = 0.f; }

    float o[8];
#pragma unroll
    for (int d = 0; d < 8; d++) o[d] = 0.f;

    int qig = tid >> 3, kjg = tid & 7;
    int qo  = tid & 63, dhg = tid >> 6;
    __syncthreads();

    for (int k0 = 0; k0 < TT; k0 += 64) {
#pragma unroll
        for (int j = 0; j < 2; j++) {
            int f = tid + j*256;
            int dhi = f >> 4, t4 = f & 15;
            *(float4*)&Ks[dhi][t4*4] = *(const float4*)(Kg + (size_t)dhi*TT + k0 + t4*4);
            float4 v = *(const float4*)(Vg + (size_t)dhi*TT + k0 + t4*4);
            Vs[t4*4+0][dhi] = v.x; Vs[t4*4+1][dhi] = v.y;
            Vs[t4*4+2][dhi] = v.z; Vs[t4*4+3][dhi] = v.w;
        }
        __syncthreads();

        float s[2][8];
#pragma unroll
        for (int i = 0; i < 2; i++)
#pragma unroll
            for (int j = 0; j < 8; j++) s[i][j] = 0.f;
#pragma unroll 8
        for (int dhi = 0; dhi < 32; dhi++) {
            float q0v = Qs[dhi][qig*2+0];
            float q1v = Qs[dhi][qig*2+1];
            float4 ka = *(const float4*)&Ks[dhi][kjg*8];
            float4 kb = *(const float4*)&Ks[dhi][kjg*8+4];
            float kv[8] = {ka.x,ka.y,ka.z,ka.w,kb.x,kb.y,kb.z,kb.w};
#pragma unroll
            for (int j = 0; j < 8; j++) {
                s[0][j] = fmaf(q0v, kv[j], s[0][j]);
                s[1][j] = fmaf(q1v, kv[j], s[1][j]);
            }
        }

        float mnew[2], alp[2], csum[2];
#pragma unroll
        for (int i = 0; i < 2; i++) {
            float m = s[i][0];
#pragma unroll
            for (int j = 1; j < 8; j++) m = fmaxf(m, s[i][j]);
            m = fmaxf(m, __shfl_xor_sync(0xffffffffu, m, 4));
            m = fmaxf(m, __shfl_xor_sync(0xffffffffu, m, 2));
            m = fmaxf(m, __shfl_xor_sync(0xffffffffu, m, 1));
            int qi = qig*2 + i;
            float mold = m_s[qi];
            mnew[i] = fmaxf(mold, m);
            alp[i]  = __expf(mold - mnew[i]);
            float cs = 0.f;
#pragma unroll
            for (int j = 0; j < 8; j++) {
                float p = __expf(s[i][j] - mnew[i]);
                Ps[qi][kjg*8+j] = p;
                cs += p;
            }
            cs += __shfl_xor_sync(0xffffffffu, cs, 4);
            cs += __shfl_xor_sync(0xffffffffu, cs, 2);
            cs += __shfl_xor_sync(0xffffffffu, cs, 1);
            csum[i] = cs;
        }
        if (kjg == 0) {
#pragma unroll
            for (int i = 0; i < 2; i++) {
                int qi = qig*2 + i;
                m_s[qi]  = mnew[i];
                l_s[qi]  = l_s[qi]*alp[i] + csum[i];
                al_s[qi] = alp[i];
            }
        }
        __syncthreads();

        float alpha = al_s[qo];
#pragma unroll
        for (int d = 0; d < 8; d++) o[d] *= alpha;
#pragma unroll 4
        for (int kj = 0; kj < 64; kj++) {
            float p = Ps[qo][kj];
            float4 va = *(const float4*)&Vs[kj][dhg*8];
            float4 vb = *(const float4*)&Vs[kj][dhg*8+4];
            o[0] = fmaf(p, va.x, o[0]); o[1] = fmaf(p, va.y, o[1]);
            o[2] = fmaf(p, va.z, o[2]); o[3] = fmaf(p, va.w, o[3]);
            o[4] = fmaf(p, vb.x, o[4]); o[5] = fmaf(p, vb.y, o[5]);
            o[6] = fmaf(p, vb.z, o[6]); o[7] = fmaf(p, vb.w, o[7]);
        }
        __syncthreads();
    }

    float linv = 1.f / l_s[qo];
    float* Og = g_attn + (size_t)bh*DHEAD*TT;
#pragma unroll
    for (int d = 0; d < 8; d++)
        Og[(size_t)(dhg*8+d)*TT + q0 + qo] = o[d]*linv;
}

// =====================================================================
// Kernel 4: output projection, scaled by tanh(gamma)
// =====================================================================
__global__ __launch_bounds__(256) void k_proj(
    const float* __restrict__ wo, const float* __restrict__ gamma)
{
    __shared__ float As[32][64];
    __shared__ float Bs[32][64];
    int tid = threadIdx.x;
    int t0 = blockIdx.x*64, d0 = blockIdx.y*64, b = blockIdx.z;
    int ng = tid & 15, mg = tid >> 4;

    float acc[4][4];
#pragma unroll
    for (int i = 0; i < 4; i++)
#pragma unroll
        for (int j = 0; j < 4; j++) acc[i][j] = 0.f;

    for (int c0 = 0; c0 < CC; c0 += 32) {
#pragma unroll
        for (int j = 0; j < 2; j++) {
            int f = tid + j*256;
            int k = f >> 4, m4 = f & 15;
            int d = c0 + k;
            const float* src = g_attn + (((size_t)b*NHEADS + (d&7))*DHEAD + (d>>3))*TT + t0 + m4*4;
            *(float4*)&As[k][m4*4] = *(const float4*)src;
            *(float4*)&Bs[k][m4*4] = *(const float4*)(wo + (size_t)d*CC + d0 + m4*4);
        }
        __syncthreads();
#pragma unroll 8
        for (int k = 0; k < 32; k++) {
            float4 a  = *(const float4*)&As[k][mg*4];
            float4 bv = *(const float4*)&Bs[k][ng*4];
            float am[4] = {a.x,a.y,a.z,a.w};
            float bn[4] = {bv.x,bv.y,bv.z,bv.w};
#pragma unroll
            for (int mm = 0; mm < 4; mm++)
#pragma unroll
                for (int nn = 0; nn < 4; nn++)
                    acc[mm][nn] = fmaf(am[mm], bn[nn], acc[mm][nn]);
        }
        __syncthreads();
    }

    float tg = tanhf(gamma[0]);
#pragma unroll
    for (int nn = 0; nn < 4; nn++) {
        int d = d0 + ng*4 + nn;
        size_t base = ((size_t)b*CC + d)*TT + t0 + mg*4;
        *(float4*)&g_proj[base] =
            make_float4(acc[0][nn]*tg, acc[1][nn]*tg, acc[2][nn]*tg, acc[3][nn]*tg);
    }
}

// =====================================================================
// Winograd F(4x4, 3x3)
// =====================================================================

// ---- W1: weight transform  U = G g G^T  -> g_U[p][ic][oc]
__device__ __forceinline__ void gfilt(const float a, const float b, const float c,
                                      float* o) {
    o[0] = 0.25f*a;
    o[1] = (-a - b - c) * (1.f/6.f);
    o[2] = (-a + b - c) * (1.f/6.f);
    o[3] = a*(1.f/24.f) + b*(1.f/12.f) + c*(1.f/6.f);
    o[4] = a*(1.f/24.f) - b*(1.f/12.f) + c*(1.f/6.f);
    o[5] = c;
}

__global__ __launch_bounds__(256) void k_wg_wt(const float* __restrict__ cw)
{
    int idx = blockIdx.x*256 + threadIdx.x;   // 0..65535
    int oc = idx & 255, ic = idx >> 8;
    const float* g = cw + (size_t)oc*2304 + ic*9;
    float g00=g[0],g01=g[1],g02=g[2],g10=g[3],g11=g[4],g12=g[5],g20=g[6],g21=g[7],g22=g[8];

    float t[6][3];
    {   // columns: T = G g (6x3)
        float o0[6], o1[6], o2[6];
        gfilt(g00, g10, g20, o0);
        gfilt(g01, g11, g21, o1);
        gfilt(g02, g12, g22, o2);
#pragma unroll
        for (int r = 0; r < 6; r++) { t[r][0]=o0[r]; t[r][1]=o1[r]; t[r][2]=o2[r]; }
    }
#pragma unroll
    for (int r = 0; r < 6; r++) {
        float o[6];
        gfilt(t[r][0], t[r][1], t[r][2], o);
#pragma unroll
        for (int c = 0; c < 6; c++)
            g_U[(size_t)(r*6+c)*CC*CC + (size_t)ic*CC + oc] = o[c];
    }
}

// ---- W2: input transform  V = B^T d B  -> g_V[p][ic][tile]
__device__ __forceinline__ void btrans(const float* d, float* o) {
    o[0] = 4.f*d[0] - 5.f*d[2] + d[4];
    o[1] = -4.f*d[1] - 4.f*d[2] + d[3] + d[4];
    o[2] =  4.f*d[1] - 4.f*d[2] - d[3] + d[4];
    o[3] = -2.f*d[1] -     d[2] + 2.f*d[3] + d[4];
    o[4] =  2.f*d[1] -     d[2] - 2.f*d[3] + d[4];
    o[5] =  4.f*d[1] - 5.f*d[3] + d[5];
}

__global__ __launch_bounds__(256) void k_wg_in(const float* __restrict__ x)
{
    int tid = threadIdx.x;
    int tx = tid & 15, ic_l = tid >> 4;
    int ty = blockIdx.x, icT = blockIdx.y, b = blockIdx.z;
    int ic = icT*16 + ic_l;
    int tile = b*256 + ty*16 + tx;

    const float* xp = x + ((size_t)b*CC + ic)*PP;
    int gy0 = ty*4 - 1, gx0 = tx*4 - 1;

    float d[6][6];
#pragma unroll
    for (int i = 0; i < 6; i++) {
        int gy = gy0 + i;
        bool yok = (unsigned)gy < 64u;
#pragma unroll
        for (int j = 0; j < 6; j++) {
            int gx = gx0 + j;
            d[i][j] = (yok && (unsigned)gx < 64u) ? xp[gy*64 + gx] : 0.f;
        }
    }
    float wcol[6][6];
#pragma unroll
    for (int j = 0; j < 6; j++) {
        float col[6] = {d[0][j], d[1][j], d[2][j], d[3][j], d[4][j], d[5][j]};
        float o[6];
        btrans(col, o);
#pragma unroll
        for (int r = 0; r < 6; r++) wcol[r][j] = o[r];
    }
#pragma unroll
    for (int r = 0; r < 6; r++) {
        float o[6];
        btrans(wcol[r], o);
#pragma unroll
        for (int c = 0; c < 6; c++)
            g_V[(size_t)(r*6+c)*CC*NTIL + (size_t)ic*NTIL + tile] = o[c];
    }
}

// ---- W3: 36 batched GEMMs  M_p[oc][tile] = sum_ic U_p[ic][oc] * V_p[ic][tile]
__global__ __launch_bounds__(256) void k_wg_gemm()
{
    __shared__ float As[32][64];
    __shared__ float Bs[32][64];
    int tid = threadIdx.x;
    int t0 = blockIdx.x*64, oc0 = blockIdx.y*64, p = blockIdx.z;
    int ng = tid & 15, mg = tid >> 4;

    const float* Vp = g_V + (size_t)p*CC*NTIL;
    const float* Up = g_U + (size_t)p*CC*CC;

    float acc[4][4];
#pragma unroll
    for (int i = 0; i < 4; i++)
#pragma unroll
        for (int j = 0; j < 4; j++) acc[i][j] = 0.f;

    for (int c0 = 0; c0 < CC; c0 += 32) {
#pragma unroll
        for (int j = 0; j < 2; j++) {
            int f = tid + j*256;
            int k = f >> 4, m4 = f & 15;
            *(float4*)&As[k][m4*4] = *(const float4*)(Vp + (size_t)(c0+k)*NTIL + t0 + m4*4);
            *(float4*)&Bs[k][m4*4] = *(const float4*)(Up + (size_t)(c0+k)*CC + oc0 + m4*4);
        }
        __syncthreads();
#pragma unroll 8
        for (int k = 0; k < 32; k++) {
            float4 a  = *(const float4*)&As[k][mg*4];
            float4 bv = *(const float4*)&Bs[k][ng*4];
            float am[4] = {a.x,a.y,a.z,a.w};
            float bn[4] = {bv.x,bv.y,bv.z,bv.w};
#pragma unroll
            for (int mm = 0; mm < 4; mm++)
#pragma unroll
                for (int nn = 0; nn < 4; nn++)
                    acc[mm][nn] = fmaf(am[mm], bn[nn], acc[mm][nn]);
        }
        __syncthreads();
    }

    float* Mp = g_M + (size_t)p*CC*NTIL;
#pragma unroll
    for (int nn = 0; nn < 4; nn++) {
        int oc = oc0 + ng*4 + nn;
        *(float4*)(Mp + (size_t)oc*NTIL + t0 + mg*4) =
            make_float4(acc[0][nn], acc[1][nn], acc[2][nn], acc[3][nn]);
    }
}

// ---- W4: output transform  Y = A^T M A  + bias + unpool-gated add -> out
__device__ __forceinline__ void atrans(const float* w, float* o) {
    o[0] = w[0] + w[1] + w[2] + w[3] + w[4];
    o[1] = w[1] - w[2] + 2.f*w[3] - 2.f*w[4];
    o[2] = w[1] + w[2] + 4.f*w[3] + 4.f*w[4];
    o[3] = w[1] - w[2] + 8.f*w[3] - 8.f*w[4] + w[5];
}

__global__ __launch_bounds__(256) void k_wg_out(
    const float* __restrict__ cb, float* __restrict__ out)
{
    int tid = threadIdx.x;
    int tx = tid & 15, oc_l = tid >> 4;
    int ty = blockIdx.x, ocT = blockIdx.y, b = blockIdx.z;
    int oc = ocT*16 + oc_l;
    int tile = b*256 + ty*16 + tx;

    float m[6][6];
#pragma unroll
    for (int r = 0; r < 6; r++)
#pragma unroll
        for (int c = 0; c < 6; c++)
            m[r][c] = g_M[(size_t)(r*6+c)*CC*NTIL + (size_t)oc*NTIL + tile];

    float z[4][6];
#pragma unroll
    for (int j = 0; j < 6; j++) {
        float col[6] = {m[0][j], m[1][j], m[2][j], m[3][j], m[4][j], m[5][j]};
        float o[4];
        atrans(col, o);
#pragma unroll
        for (int i = 0; i < 4; i++) z[i][j] = o[i];
    }

    float bias = cb[oc];
    size_t chan = (size_t)b*CC + oc;
    const unsigned char* idxp  = g_idx  + chan*TT;
    const float*         projp = g_proj + chan*TT;
    float* op = out + chan*PP;

#pragma unroll
    for (int r = 0; r < 4; r++) {
        float y[4];
        atrans(z[r], y);
        int gy = ty*4 + r;
        int h2 = gy >> 1;
        int subr = (gy & 1) << 1;
        float v[4];
#pragma unroll
        for (int c = 0; c < 4; c++) {
            int gx = tx*4 + c;
            float vv = y[c] + bias;
            int w2 = gx >> 1;
            if (idxp[h2*32 + w2] == (unsigned char)(subr | (gx & 1)))
                vv += projp[h2*32 + w2];
            v[c] = vv;
        }
        *(float4*)(op + (size_t)gy*64 + tx*4) = make_float4(v[0], v[1], v[2], v[3]);
    }
}

// =====================================================================
extern "C" void kernel_launch(void* const* d_in, const int* in_sizes, int n_in,
                              void* d_out, int out_size)
{
    const float* x      = (const float*)d_in[0];
    const float* conv_w = (const float*)d_in[1];
    const float* conv_b = (const float*)d_in[2];
    const float* fr_w   = (const float*)d_in[3];
    const float* fr_b   = (const float*)d_in[4];
    const float* wq     = (const float*)d_in[5];
    const float* wk     = (const float*)d_in[6];
    const float* wv     = (const float*)d_in[7];
    const float* wo     = (const float*)d_in[8];
    const float* gamma  = (const float*)d_in[9];
    float* out = (float*)d_out;

    // side stream + fork/join events (created once; host-side objects only)
    static cudaStream_t s1 = [](){
        cudaStream_t s; cudaStreamCreateWithFlags(&s, cudaStreamNonBlocking); return s; }();
    static cudaEvent_t ev_fork = [](){
        cudaEvent_t e; cudaEventCreateWithFlags(&e, cudaEventDisableTiming); return e; }();
    static cudaEvent_t ev_join = [](){
        cudaEvent_t e; cudaEventCreateWithFlags(&e, cudaEventDisableTiming); return e; }();

    // fork: Winograd produce chain on s1, attention chain on default stream
    cudaEventRecord(ev_fork, 0);
    cudaStreamWaitEvent(s1, ev_fork, 0);

    k_wg_wt   <<<256, 256, 0, s1>>>(conv_w);
    k_wg_in   <<<dim3(16, 16, BB),       256, 0, s1>>>(x);
    k_wg_gemm <<<dim3(64, 4, 36),        256, 0, s1>>>();
    cudaEventRecord(ev_join, s1);

    k_fr_pool <<<dim3(32, 4, BB),        256>>>(x, fr_w, fr_b);
    k_qkv     <<<dim3(16, 4, BB),        256>>>(wq, wk, wv);
    k_attn    <<<dim3(16, BB*NHEADS, 1), 256>>>();
    k_proj    <<<dim3(16, 4, BB),        256>>>(wo, gamma);

    // join: wg_out needs g_M (s1) and g_idx/g_proj (default)
    cudaStreamWaitEvent(0, ev_join, 0);
    k_wg_out  <<<dim3(16, 16, BB),       256>>>(conv_b, out);
}

// round 13
// speedup vs baseline: 2.5354x; 1.0299x over previous
#include <cuda_runtime.h>
#include <math.h>
#include <stdint.h>

#define BB     16
#define CC     256
#define HH     64
#define WWID   64
#define PP     4096   // HH*WWID
#define TT     1024   // 32*32 pooled tokens
#define NHEADS 8
#define DHEAD  32
#define NTIL   4096   // 16 b * 256 tiles (16x16 tiles of 4x4 outputs)

// ---------------- scratch (device globals; no allocs allowed) ----------------
__device__ float         g_pooled[BB*CC*TT];           // [b][c][t]
__device__ unsigned char g_idx   [BB*CC*TT];           // argmax 0..3
__device__ float         g_q   [BB*NHEADS*DHEAD*TT];   // [bh][dhi][t]
__device__ float         g_k   [BB*NHEADS*DHEAD*TT];
__device__ float         g_v   [BB*NHEADS*DHEAD*TT];
__device__ float         g_attn[BB*NHEADS*DHEAD*TT];   // [bh][dhi][t]
__device__ float         g_proj[BB*CC*TT];             // [b][c][t], pre-scaled by tanh(gamma)
__device__ float         g_U[36*CC*CC];                // [p][ic][oc]
__device__ float         g_V[36*CC*NTIL];              // [p][ic][tile]
__device__ float         g_M[36*CC*NTIL];              // [p][oc][tile]

// ---------------- tf32 mma helpers (fragment mapping validated in R2) -------
__device__ __forceinline__ float f2tf(float v) {
    uint32_t u;
    asm("cvt.rna.tf32.f32 %0, %1;" : "=r"(u) : "f"(v));
    return __uint_as_float(u);
}
__device__ __forceinline__ void mma_tf32(float4& c, const uint32_t* a, uint2 b) {
    asm volatile(
        "mma.sync.aligned.m16n8k8.row.col.f32.tf32.tf32.f32 "
        "{%0,%1,%2,%3}, {%4,%5,%6,%7}, {%8,%9}, {%0,%1,%2,%3};"
        : "+f"(c.x), "+f"(c.y), "+f"(c.z), "+f"(c.w)
        : "r"(a[0]), "r"(a[1]), "r"(a[2]), "r"(a[3]), "r"(b.x), "r"(b.y));
}

// =====================================================================
// Kernel 1: 1x1 conv (feature reduce) + bias + 2x2 maxpool with indices
// (fp32 — argmax indices are discrete, must match reference exactly)
// =====================================================================
__global__ __launch_bounds__(256) void k_fr_pool(
    const float* __restrict__ x, const float* __restrict__ frw,
    const float* __restrict__ frb)
{
    __shared__ float Xs[32][128];
    __shared__ float Ws[64][32];
    int tid = threadIdx.x;
    int hp = blockIdx.x, ocT = blockIdx.y, b = blockIdx.z;
    int oc0 = ocT * 64;
    int ocg = tid >> 5;
    int pxg = tid & 31;

    float acc[8][4];
#pragma unroll
    for (int i = 0; i < 8; i++)
#pragma unroll
        for (int j = 0; j < 4; j++) acc[i][j] = 0.f;

    const float* xb = x + (size_t)b*CC*PP + hp*128;

    for (int c0 = 0; c0 < CC; c0 += 32) {
#pragma unroll
        for (int j = 0; j < 4; j++) {
            int f = tid + j*256;
            int k = f >> 5, c4 = f & 31;
            *(float4*)&Xs[k][c4*4] = *(const float4*)(xb + (size_t)(c0+k)*PP + c4*4);
        }
#pragma unroll
        for (int j = 0; j < 8; j++) {
            int f = tid + j*256;
            int oc = f >> 5, k = f & 31;
            Ws[oc][k] = frw[(size_t)(oc0+oc)*CC + c0 + k];
        }
        __syncthreads();
#pragma unroll 8
        for (int k = 0; k < 32; k++) {
            float4 xv = *(const float4*)&Xs[k][pxg*4];
#pragma unroll
            for (int i = 0; i < 8; i++) {
                float w = Ws[ocg*8+i][k];
                acc[i][0] = fmaf(w, xv.x, acc[i][0]);
                acc[i][1] = fmaf(w, xv.y, acc[i][1]);
                acc[i][2] = fmaf(w, xv.z, acc[i][2]);
                acc[i][3] = fmaf(w, xv.w, acc[i][3]);
            }
        }
        __syncthreads();
    }

    bool low = (pxg < 16);
#pragma unroll
    for (int i = 0; i < 8; i++) {
        int oc = oc0 + ocg*8 + i;
        float bi = frb[oc];
        float a0 = acc[i][0]+bi, a1 = acc[i][1]+bi;
        float a2 = acc[i][2]+bi, a3 = acc[i][3]+bi;
        float p0 = __shfl_xor_sync(0xffffffffu, a0, 16);
        float p1 = __shfl_xor_sync(0xffffffffu, a1, 16);
        float p2 = __shfl_xor_sync(0xffffffffu, a2, 16);
        float p3 = __shfl_xor_sync(0xffffffffu, a3, 16);
        if (low) {
            size_t base = ((size_t)b*CC + oc)*TT + hp*32 + pxg*2;
            {   float best = a0; int am = 0;
                if (a1 > best) { best = a1; am = 1; }
                if (p0 > best) { best = p0; am = 2; }
                if (p1 > best) { best = p1; am = 3; }
                g_pooled[base] = best; g_idx[base] = (unsigned char)am; }
            {   float best = a2; int am = 0;
                if (a3 > best) { best = a3; am = 1; }
                if (p2 > best) { best = p2; am = 2; }
                if (p3 > best) { best = p3; am = 3; }
                g_pooled[base+1] = best; g_idx[base+1] = (unsigned char)am; }
        }
    }
}

// =====================================================================
// Kernel 2: QKV projection via mma.sync tf32.
// C[d][t] = sum_c W[c][d] * pooled[c][t]; m=d(64), n=t(128), k=c(256).
// Block 256 thr = 8 warps (2m x 4n); warp m32 x n32; double-buffered smem.
// Grid (8 tT, 3 mats x 4 dT, 16 b). Attention branch is diluted by
// tanh(gamma) ~0.1 at the output, so tf32 error (~2e-4) lands ~1e-5 final.
// =====================================================================
__global__ __launch_bounds__(256, 2) void k_qkv_mma(
    const float* __restrict__ wq, const float* __restrict__ wk,
    const float* __restrict__ wv)
{
    __shared__ float As[2][2][64][8];   // [stage][kslice][m][2c+hi], k = c+hi*4
    __shared__ float Bs[2][16][136];    // [stage][k][n], pad 8 -> conflict-free
    int tid = threadIdx.x;
    int lane = tid & 31, w = tid >> 5;
    int r = lane >> 2, cq = lane & 3;
    int wm = w >> 2, wn = w & 3;
    int t0 = blockIdx.x * 128;
    int mat = blockIdx.y >> 2, dT = blockIdx.y & 3;
    int b = blockIdx.z;
    int m0 = dT * 64;

    const float* W  = (mat == 0) ? wq : (mat == 1) ? wk : wv;
    const float* Bg = g_pooled + (size_t)b*CC*TT;

    // staging maps
    int a_kk = tid >> 4, a_m = (tid & 15) * 4;               // A: 1 float4/thread
    int a_col = ((a_kk & 3) << 1) | ((a_kk >> 2) & 1);
    int a_ks  = a_kk >> 3;
    int b_kk0 = tid >> 5,        b_tq0 = (tid & 31) * 4;     // B: 2 float4/thread
    int b_kk1 = (tid >> 5) + 8,  b_tq1 = b_tq0;

    float4 acc[2][4];
#pragma unroll
    for (int mt = 0; mt < 2; mt++)
#pragma unroll
        for (int nt = 0; nt < 4; nt++) acc[mt][nt] = make_float4(0.f,0.f,0.f,0.f);

    float4 ra, rb0, rb1;
    // prolog: load step0, store stage0
    ra  = *(const float4*)(W  + (size_t)a_kk*CC + m0 + a_m);
    rb0 = *(const float4*)(Bg + (size_t)b_kk0*TT + t0 + b_tq0);
    rb1 = *(const float4*)(Bg + (size_t)b_kk1*TT + t0 + b_tq1);
    As[0][a_ks][a_m+0][a_col] = f2tf(ra.x);
    As[0][a_ks][a_m+1][a_col] = f2tf(ra.y);
    As[0][a_ks][a_m+2][a_col] = f2tf(ra.z);
    As[0][a_ks][a_m+3][a_col] = f2tf(ra.w);
    *(float4*)&Bs[0][b_kk0][b_tq0] = make_float4(f2tf(rb0.x), f2tf(rb0.y), f2tf(rb0.z), f2tf(rb0.w));
    *(float4*)&Bs[0][b_kk1][b_tq1] = make_float4(f2tf(rb1.x), f2tf(rb1.y), f2tf(rb1.z), f2tf(rb1.w));
    __syncthreads();
    // prefetch step1
    ra  = *(const float4*)(W  + (size_t)(16 + a_kk)*CC + m0 + a_m);
    rb0 = *(const float4*)(Bg + (size_t)(16 + b_kk0)*TT + t0 + b_tq0);
    rb1 = *(const float4*)(Bg + (size_t)(16 + b_kk1)*TT + t0 + b_tq1);

    for (int s = 0; s < 16; s++) {
        int cur = s & 1;
        // compute on buf cur
#pragma unroll
        for (int ks = 0; ks < 2; ks++) {
            uint32_t a[2][4];
#pragma unroll
            for (int mt = 0; mt < 2; mt++) {
                int mb = wm*32 + mt*16;
                float2 lo = *(const float2*)&As[cur][ks][mb + r][cq*2];
                float2 hi = *(const float2*)&As[cur][ks][mb + r + 8][cq*2];
                a[mt][0] = __float_as_uint(lo.x); a[mt][1] = __float_as_uint(hi.x);
                a[mt][2] = __float_as_uint(lo.y); a[mt][3] = __float_as_uint(hi.y);
            }
#pragma unroll
            for (int nt = 0; nt < 4; nt++) {
                int nb = wn*32 + nt*8 + r;
                uint2 bf;
                bf.x = __float_as_uint(Bs[cur][ks*8 + cq][nb]);
                bf.y = __float_as_uint(Bs[cur][ks*8 + cq + 4][nb]);
                mma_tf32(acc[0][nt], a[0], bf);
                mma_tf32(acc[1][nt], a[1], bf);
            }
        }
        if (s < 15) {
            __syncthreads();
            int nxt = cur ^ 1;
            As[nxt][a_ks][a_m+0][a_col] = f2tf(ra.x);
            As[nxt][a_ks][a_m+1][a_col] = f2tf(ra.y);
            As[nxt][a_ks][a_m+2][a_col] = f2tf(ra.z);
            As[nxt][a_ks][a_m+3][a_col] = f2tf(ra.w);
            *(float4*)&Bs[nxt][b_kk0][b_tq0] = make_float4(f2tf(rb0.x), f2tf(rb0.y), f2tf(rb0.z), f2tf(rb0.w));
            *(float4*)&Bs[nxt][b_kk1][b_tq1] = make_float4(f2tf(rb1.x), f2tf(rb1.y), f2tf(rb1.z), f2tf(rb1.w));
            if (s < 14) {
                int k0 = (s + 2) * 16;
                ra  = *(const float4*)(W  + (size_t)(k0 + a_kk)*CC + m0 + a_m);
                rb0 = *(const float4*)(Bg + (size_t)(k0 + b_kk0)*TT + t0 + b_tq0);
                rb1 = *(const float4*)(Bg + (size_t)(k0 + b_kk1)*TT + t0 + b_tq1);
            }
            __syncthreads();
        }
    }

    // epilogue: rows d (head-interleaved), cols t; STG.64 (32B sectors/quad)
    float* O = (mat == 0) ? g_q : (mat == 1) ? g_k : g_v;
#pragma unroll
    for (int mt = 0; mt < 2; mt++) {
        int dbase = m0 + wm*32 + mt*16;
#pragma unroll
        for (int nt = 0; nt < 4; nt++) {
            float4 c = acc[mt][nt];
            int t  = t0 + wn*32 + nt*8 + cq*2;
            int d1 = dbase + r, d2 = dbase + r + 8;
            size_t a1 = (((size_t)b*NHEADS + (d1 & 7))*DHEAD + (d1 >> 3))*TT + t;
            size_t a2 = (((size_t)b*NHEADS + (d2 & 7))*DHEAD + (d2 >> 3))*TT + t;
            *(float2*)&O[a1] = make_float2(c.x, c.y);
            *(float2*)&O[a2] = make_float2(c.z, c.w);
        }
    }
}

// =====================================================================
// Kernel 3: flash attention (unchanged)
// =====================================================================
__global__ __launch_bounds__(256) void k_attn()
{
    __shared__ float Qs[32][64];
    __shared__ float Ks[32][64];
    __shared__ float Vs[64][36];
    __shared__ float Ps[64][65];
    __shared__ float m_s[64], l_s[64], al_s[64];

    int tid = threadIdx.x;
    int q0 = blockIdx.x*64; int bh = blockIdx.y;
    const float* Qg = g_q + (size_t)bh*DHEAD*TT;
    const float* Kg = g_k + (size_t)bh*DHEAD*TT;
    const float* Vg = g_v + (size_t)bh*DHEAD*TT;
    const float qscale = 0.17677669529663687f;

#pragma unroll
    for (int j = 0; j < 2; j++) {
        int f = tid + j*256;
        int dhi = f >> 4, t4 = f & 15;
        float4 v = *(const float4*)(Qg + (size_t)dhi*TT + q0 + t4*4);
        v.x *= qscale; v.y *= qscale; v.z *= qscale; v.w *= qscale;
        *(float4*)&Qs[dhi][t4*4] = v;
    }
    if (tid < 64) { m_s[tid] = -3.0e38f; l_s[tid] = 0.f; }

    float o[8];
#pragma unroll
    for (int d = 0; d < 8; d++) o[d] = 0.f;

    int qig = tid >> 3, kjg = tid & 7;
    int qo  = tid & 63, dhg = tid >> 6;
    __syncthreads();

    for (int k0 = 0; k0 < TT; k0 += 64) {
#pragma unroll
        for (int j = 0; j < 2; j++) {
            int f = tid + j*256;
            int dhi = f >> 4, t4 = f & 15;
            *(float4*)&Ks[dhi][t4*4] = *(const float4*)(Kg + (size_t)dhi*TT + k0 + t4*4);
            float4 v = *(const float4*)(Vg + (size_t)dhi*TT + k0 + t4*4);
            Vs[t4*4+0][dhi] = v.x; Vs[t4*4+1][dhi] = v.y;
            Vs[t4*4+2][dhi] = v.z; Vs[t4*4+3][dhi] = v.w;
        }
        __syncthreads();

        float s[2][8];
#pragma unroll
        for (int i = 0; i < 2; i++)
#pragma unroll
            for (int j = 0; j < 8; j++) s[i][j] = 0.f;
#pragma unroll 8
        for (int dhi = 0; dhi < 32; dhi++) {
            float q0v = Qs[dhi][qig*2+0];
            float q1v = Qs[dhi][qig*2+1];
            float4 ka = *(const float4*)&Ks[dhi][kjg*8];
            float4 kb = *(const float4*)&Ks[dhi][kjg*8+4];
            float kv[8] = {ka.x,ka.y,ka.z,ka.w,kb.x,kb.y,kb.z,kb.w};
#pragma unroll
            for (int j = 0; j < 8; j++) {
                s[0][j] = fmaf(q0v, kv[j], s[0][j]);
                s[1][j] = fmaf(q1v, kv[j], s[1][j]);
            }
        }

        float mnew[2], alp[2], csum[2];
#pragma unroll
        for (int i = 0; i < 2; i++) {
            float m = s[i][0];
#pragma unroll
            for (int j = 1; j < 8; j++) m = fmaxf(m, s[i][j]);
            m = fmaxf(m, __shfl_xor_sync(0xffffffffu, m, 4));
            m = fmaxf(m, __shfl_xor_sync(0xffffffffu, m, 2));
            m = fmaxf(m, __shfl_xor_sync(0xffffffffu, m, 1));
            int qi = qig*2 + i;
            float mold = m_s[qi];
            mnew[i] = fmaxf(mold, m);
            alp[i]  = __expf(mold - mnew[i]);
            float cs = 0.f;
#pragma unroll
            for (int j = 0; j < 8; j++) {
                float p = __expf(s[i][j] - mnew[i]);
                Ps[qi][kjg*8+j] = p;
                cs += p;
            }
            cs += __shfl_xor_sync(0xffffffffu, cs, 4);
            cs += __shfl_xor_sync(0xffffffffu, cs, 2);
            cs += __shfl_xor_sync(0xffffffffu, cs, 1);
            csum[i] = cs;
        }
        if (kjg == 0) {
#pragma unroll
            for (int i = 0; i < 2; i++) {
                int qi = qig*2 + i;
                m_s[qi]  = mnew[i];
                l_s[qi]  = l_s[qi]*alp[i] + csum[i];
                al_s[qi] = alp[i];
            }
        }
        __syncthreads();

        float alpha = al_s[qo];
#pragma unroll
        for (int d = 0; d < 8; d++) o[d] *= alpha;
#pragma unroll 4
        for (int kj = 0; kj < 64; kj++) {
            float p = Ps[qo][kj];
            float4 va = *(const float4*)&Vs[kj][dhg*8];
            float4 vb = *(const float4*)&Vs[kj][dhg*8+4];
            o[0] = fmaf(p, va.x, o[0]); o[1] = fmaf(p, va.y, o[1]);
            o[2] = fmaf(p, va.z, o[2]); o[3] = fmaf(p, va.w, o[3]);
            o[4] = fmaf(p, vb.x, o[4]); o[5] = fmaf(p, vb.y, o[5]);
            o[6] = fmaf(p, vb.z, o[6]); o[7] = fmaf(p, vb.w, o[7]);
        }
        __syncthreads();
    }

    float linv = 1.f / l_s[qo];
    float* Og = g_attn + (size_t)bh*DHEAD*TT;
#pragma unroll
    for (int d = 0; d < 8; d++)
        Og[(size_t)(dhg*8+d)*TT + q0 + qo] = o[d]*linv;
}

// =====================================================================
// Kernel 4: output projection via mma.sync tf32, scaled by tanh(gamma).
// C[d][t] = sum_c wo[c][d] * attn_merged[c][t]; same template as k_qkv_mma.
// Output g_proj[b][d][t] is direct [m][n] — no transpose needed.
// =====================================================================
__global__ __launch_bounds__(256, 2) void k_proj_mma(
    const float* __restrict__ wo, const float* __restrict__ gamma)
{
    __shared__ float As[2][2][64][8];
    __shared__ float Bs[2][16][136];
    int tid = threadIdx.x;
    int lane = tid & 31, w = tid >> 5;
    int r = lane >> 2, cq = lane & 3;
    int wm = w >> 2, wn = w & 3;
    int t0 = blockIdx.x * 128;
    int dT = blockIdx.y;
    int b = blockIdx.z;
    int m0 = dT * 64;

    int a_kk = tid >> 4, a_m = (tid & 15) * 4;
    int a_col = ((a_kk & 3) << 1) | ((a_kk >> 2) & 1);
    int a_ks  = a_kk >> 3;
    int b_kk0 = tid >> 5,       b_tq0 = (tid & 31) * 4;
    int b_kk1 = (tid >> 5) + 8, b_tq1 = b_tq0;

    // attn row gather: row c -> g_attn[(b*8+(c&7))*32 + (c>>3)][t]
    #define ATTN_ROW(c) (g_attn + (((size_t)b*NHEADS + ((c) & 7))*DHEAD + ((c) >> 3))*TT)

    float4 acc[2][4];
#pragma unroll
    for (int mt = 0; mt < 2; mt++)
#pragma unroll
        for (int nt = 0; nt < 4; nt++) acc[mt][nt] = make_float4(0.f,0.f,0.f,0.f);

    float4 ra, rb0, rb1;
    ra  = *(const float4*)(wo + (size_t)a_kk*CC + m0 + a_m);
    rb0 = *(const float4*)(ATTN_ROW(b_kk0) + t0 + b_tq0);
    rb1 = *(const float4*)(ATTN_ROW(b_kk1) + t0 + b_tq1);
    As[0][a_ks][a_m+0][a_col] = f2tf(ra.x);
    As[0][a_ks][a_m+1][a_col] = f2tf(ra.y);
    As[0][a_ks][a_m+2][a_col] = f2tf(ra.z);
    As[0][a_ks][a_m+3][a_col] = f2tf(ra.w);
    *(float4*)&Bs[0][b_kk0][b_tq0] = make_float4(f2tf(rb0.x), f2tf(rb0.y), f2tf(rb0.z), f2tf(rb0.w));
    *(float4*)&Bs[0][b_kk1][b_tq1] = make_float4(f2tf(rb1.x), f2tf(rb1.y), f2tf(rb1.z), f2tf(rb1.w));
    __syncthreads();
    ra  = *(const float4*)(wo + (size_t)(16 + a_kk)*CC + m0 + a_m);
    rb0 = *(const float4*)(ATTN_ROW(16 + b_kk0) + t0 + b_tq0);
    rb1 = *(const float4*)(ATTN_ROW(16 + b_kk1) + t0 + b_tq1);

    for (int s = 0; s < 16; s++) {
        int cur = s & 1;
#pragma unroll
        for (int ks = 0; ks < 2; ks++) {
            uint32_t a[2][4];
#pragma unroll
            for (int mt = 0; mt < 2; mt++) {
                int mb = wm*32 + mt*16;
                float2 lo = *(const float2*)&As[cur][ks][mb + r][cq*2];
                float2 hi = *(const float2*)&As[cur][ks][mb + r + 8][cq*2];
                a[mt][0] = __float_as_uint(lo.x); a[mt][1] = __float_as_uint(hi.x);
                a[mt][2] = __float_as_uint(lo.y); a[mt][3] = __float_as_uint(hi.y);
            }
#pragma unroll
            for (int nt = 0; nt < 4; nt++) {
                int nb = wn*32 + nt*8 + r;
                uint2 bf;
                bf.x = __float_as_uint(Bs[cur][ks*8 + cq][nb]);
                bf.y = __float_as_uint(Bs[cur][ks*8 + cq + 4][nb]);
                mma_tf32(acc[0][nt], a[0], bf);
                mma_tf32(acc[1][nt], a[1], bf);
            }
        }
        if (s < 15) {
            __syncthreads();
            int nxt = cur ^ 1;
            As[nxt][a_ks][a_m+0][a_col] = f2tf(ra.x);
            As[nxt][a_ks][a_m+1][a_col] = f2tf(ra.y);
            As[nxt][a_ks][a_m+2][a_col] = f2tf(ra.z);
            As[nxt][a_ks][a_m+3][a_col] = f2tf(ra.w);
            *(float4*)&Bs[nxt][b_kk0][b_tq0] = make_float4(f2tf(rb0.x), f2tf(rb0.y), f2tf(rb0.z), f2tf(rb0.w));
            *(float4*)&Bs[nxt][b_kk1][b_tq1] = make_float4(f2tf(rb1.x), f2tf(rb1.y), f2tf(rb1.z), f2tf(rb1.w));
            if (s < 14) {
                int k0 = (s + 2) * 16;
                ra  = *(const float4*)(wo + (size_t)(k0 + a_kk)*CC + m0 + a_m);
                rb0 = *(const float4*)(ATTN_ROW(k0 + b_kk0) + t0 + b_tq0);
                rb1 = *(const float4*)(ATTN_ROW(k0 + b_kk1) + t0 + b_tq1);
            }
            __syncthreads();
        }
    }
    #undef ATTN_ROW

    float tg = tanhf(gamma[0]);
#pragma unroll
    for (int mt = 0; mt < 2; mt++) {
        int dbase = m0 + wm*32 + mt*16;
#pragma unroll
        for (int nt = 0; nt < 4; nt++) {
            float4 c = acc[mt][nt];
            int t  = t0 + wn*32 + nt*8 + cq*2;
            size_t a1 = ((size_t)b*CC + dbase + r)*TT + t;
            size_t a2 = ((size_t)b*CC + dbase + r + 8)*TT + t;
            *(float2*)&g_proj[a1] = make_float2(c.x*tg, c.y*tg);
            *(float2*)&g_proj[a2] = make_float2(c.z*tg, c.w*tg);
        }
    }
}

// =====================================================================
// Winograd F(4x4, 3x3)  (unchanged — fp32; tf32 would land ~9e-4, too risky)
// =====================================================================
__device__ __forceinline__ void gfilt(const float a, const float b, const float c,
                                      float* o) {
    o[0] = 0.25f*a;
    o[1] = (-a - b - c) * (1.f/6.f);
    o[2] = (-a + b - c) * (1.f/6.f);
    o[3] = a*(1.f/24.f) + b*(1.f/12.f) + c*(1.f/6.f);
    o[4] = a*(1.f/24.f) - b*(1.f/12.f) + c*(1.f/6.f);
    o[5] = c;
}

__global__ __launch_bounds__(256) void k_wg_wt(const float* __restrict__ cw)
{
    int idx = blockIdx.x*256 + threadIdx.x;
    int oc = idx & 255, ic = idx >> 8;
    const float* g = cw + (size_t)oc*2304 + ic*9;
    float g00=g[0],g01=g[1],g02=g[2],g10=g[3],g11=g[4],g12=g[5],g20=g[6],g21=g[7],g22=g[8];

    float t[6][3];
    {
        float o0[6], o1[6], o2[6];
        gfilt(g00, g10, g20, o0);
        gfilt(g01, g11, g21, o1);
        gfilt(g02, g12, g22, o2);
#pragma unroll
        for (int r = 0; r < 6; r++) { t[r][0]=o0[r]; t[r][1]=o1[r]; t[r][2]=o2[r]; }
    }
#pragma unroll
    for (int r = 0; r < 6; r++) {
        float o[6];
        gfilt(t[r][0], t[r][1], t[r][2], o);
#pragma unroll
        for (int c = 0; c < 6; c++)
            g_U[(size_t)(r*6+c)*CC*CC + (size_t)ic*CC + oc] = o[c];
    }
}

__device__ __forceinline__ void btrans(const float* d, float* o) {
    o[0] = 4.f*d[0] - 5.f*d[2] + d[4];
    o[1] = -4.f*d[1] - 4.f*d[2] + d[3] + d[4];
    o[2] =  4.f*d[1] - 4.f*d[2] - d[3] + d[4];
    o[3] = -2.f*d[1] -     d[2] + 2.f*d[3] + d[4];
    o[4] =  2.f*d[1] -     d[2] - 2.f*d[3] + d[4];
    o[5] =  4.f*d[1] - 5.f*d[3] + d[5];
}

__global__ __launch_bounds__(256) void k_wg_in(const float* __restrict__ x)
{
    int tid = threadIdx.x;
    int tx = tid & 15, ic_l = tid >> 4;
    int ty = blockIdx.x, icT = blockIdx.y, b = blockIdx.z;
    int ic = icT*16 + ic_l;
    int tile = b*256 + ty*16 + tx;

    const float* xp = x + ((size_t)b*CC + ic)*PP;
    int gy0 = ty*4 - 1, gx0 = tx*4 - 1;

    float d[6][6];
#pragma unroll
    for (int i = 0; i < 6; i++) {
        int gy = gy0 + i;
        bool yok = (unsigned)gy < 64u;
#pragma unroll
        for (int j = 0; j < 6; j++) {
            int gx = gx0 + j;
            d[i][j] = (yok && (unsigned)gx < 64u) ? xp[gy*64 + gx] : 0.f;
        }
    }
    float wcol[6][6];
#pragma unroll
    for (int j = 0; j < 6; j++) {
        float col[6] = {d[0][j], d[1][j], d[2][j], d[3][j], d[4][j], d[5][j]};
        float o[6];
        btrans(col, o);
#pragma unroll
        for (int r = 0; r < 6; r++) wcol[r][j] = o[r];
    }
#pragma unroll
    for (int r = 0; r < 6; r++) {
        float o[6];
        btrans(wcol[r], o);
#pragma unroll
        for (int c = 0; c < 6; c++)
            g_V[(size_t)(r*6+c)*CC*NTIL + (size_t)ic*NTIL + tile] = o[c];
    }
}

__global__ __launch_bounds__(256) void k_wg_gemm()
{
    __shared__ float As[32][64];
    __shared__ float Bs[32][64];
    int tid = threadIdx.x;
    int t0 = blockIdx.x*64, oc0 = blockIdx.y*64, p = blockIdx.z;
    int ng = tid & 15, mg = tid >> 4;

    const float* Vp = g_V + (size_t)p*CC*NTIL;
    const float* Up = g_U + (size_t)p*CC*CC;

    float acc[4][4];
#pragma unroll
    for (int i = 0; i < 4; i++)
#pragma unroll
        for (int j = 0; j < 4; j++) acc[i][j] = 0.f;

    for (int c0 = 0; c0 < CC; c0 += 32) {
#pragma unroll
        for (int j = 0; j < 2; j++) {
            int f = tid + j*256;
            int k = f >> 4, m4 = f & 15;
            *(float4*)&As[k][m4*4] = *(const float4*)(Vp + (size_t)(c0+k)*NTIL + t0 + m4*4);
            *(float4*)&Bs[k][m4*4] = *(const float4*)(Up + (size_t)(c0+k)*CC + oc0 + m4*4);
        }
        __syncthreads();
#pragma unroll 8
        for (int k = 0; k < 32; k++) {
            float4 a  = *(const float4*)&As[k][mg*4];
            float4 bv = *(const float4*)&Bs[k][ng*4];
            float am[4] = {a.x,a.y,a.z,a.w};
            float bn[4] = {bv.x,bv.y,bv.z,bv.w};
#pragma unroll
            for (int mm = 0; mm < 4; mm++)
#pragma unroll
                for (int nn = 0; nn < 4; nn++)
                    acc[mm][nn] = fmaf(am[mm], bn[nn], acc[mm][nn]);
        }
        __syncthreads();
    }

    float* Mp = g_M + (size_t)p*CC*NTIL;
#pragma unroll
    for (int nn = 0; nn < 4; nn++) {
        int oc = oc0 + ng*4 + nn;
        *(float4*)(Mp + (size_t)oc*NTIL + t0 + mg*4) =
            make_float4(acc[0][nn], acc[1][nn], acc[2][nn], acc[3][nn]);
    }
}

__device__ __forceinline__ void atrans(const float* w, float* o) {
    o[0] = w[0] + w[1] + w[2] + w[3] + w[4];
    o[1] = w[1] - w[2] + 2.f*w[3] - 2.f*w[4];
    o[2] = w[1] + w[2] + 4.f*w[3] + 4.f*w[4];
    o[3] = w[1] - w[2] + 8.f*w[3] - 8.f*w[4] + w[5];
}

__global__ __launch_bounds__(256) void k_wg_out(
    const float* __restrict__ cb, float* __restrict__ out)
{
    int tid = threadIdx.x;
    int tx = tid & 15, oc_l = tid >> 4;
    int ty = blockIdx.x, ocT = blockIdx.y, b = blockIdx.z;
    int oc = ocT*16 + oc_l;
    int tile = b*256 + ty*16 + tx;

    float m[6][6];
#pragma unroll
    for (int r = 0; r < 6; r++)
#pragma unroll
        for (int c = 0; c < 6; c++)
            m[r][c] = g_M[(size_t)(r*6+c)*CC*NTIL + (size_t)oc*NTIL + tile];

    float z[4][6];
#pragma unroll
    for (int j = 0; j < 6; j++) {
        float col[6] = {m[0][j], m[1][j], m[2][j], m[3][j], m[4][j], m[5][j]};
        float o[4];
        atrans(col, o);
#pragma unroll
        for (int i = 0; i < 4; i++) z[i][j] = o[i];
    }

    float bias = cb[oc];
    size_t chan = (size_t)b*CC + oc;
    const unsigned char* idxp  = g_idx  + chan*TT;
    const float*         projp = g_proj + chan*TT;
    float* op = out + chan*PP;

#pragma unroll
    for (int r = 0; r < 4; r++) {
        float y[4];
        atrans(z[r], y);
        int gy = ty*4 + r;
        int h2 = gy >> 1;
        int subr = (gy & 1) << 1;
        float v[4];
#pragma unroll
        for (int c = 0; c < 4; c++) {
            int gx = tx*4 + c;
            float vv = y[c] + bias;
            int w2 = gx >> 1;
            if (idxp[h2*32 + w2] == (unsigned char)(subr | (gx & 1)))
                vv += projp[h2*32 + w2];
            v[c] = vv;
        }
        *(float4*)(op + (size_t)gy*64 + tx*4) = make_float4(v[0], v[1], v[2], v[3]);
    }
}

// =====================================================================
extern "C" void kernel_launch(void* const* d_in, const int* in_sizes, int n_in,
                              void* d_out, int out_size)
{
    const float* x      = (const float*)d_in[0];
    const float* conv_w = (const float*)d_in[1];
    const float* conv_b = (const float*)d_in[2];
    const float* fr_w   = (const float*)d_in[3];
    const float* fr_b   = (const float*)d_in[4];
    const float* wq     = (const float*)d_in[5];
    const float* wk     = (const float*)d_in[6];
    const float* wv     = (const float*)d_in[7];
    const float* wo     = (const float*)d_in[8];
    const float* gamma  = (const float*)d_in[9];
    float* out = (float*)d_out;

    static cudaStream_t s1 = [](){
        cudaStream_t s; cudaStreamCreateWithFlags(&s, cudaStreamNonBlocking); return s; }();
    static cudaEvent_t ev_fork = [](){
        cudaEvent_t e; cudaEventCreateWithFlags(&e, cudaEventDisableTiming); return e; }();
    static cudaEvent_t ev_join = [](){
        cudaEvent_t e; cudaEventCreateWithFlags(&e, cudaEventDisableTiming); return e; }();

    cudaEventRecord(ev_fork, 0);
    cudaStreamWaitEvent(s1, ev_fork, 0);

    k_wg_wt   <<<256, 256, 0, s1>>>(conv_w);
    k_wg_in   <<<dim3(16, 16, BB),       256, 0, s1>>>(x);
    k_wg_gemm <<<dim3(64, 4, 36),        256, 0, s1>>>();
    cudaEventRecord(ev_join, s1);

    k_fr_pool  <<<dim3(32, 4, BB),        256>>>(x, fr_w, fr_b);
    k_qkv_mma  <<<dim3(8, 12, BB),        256>>>(wq, wk, wv);
    k_attn     <<<dim3(16, BB*NHEADS, 1), 256>>>();
    k_proj_mma <<<dim3(8, 4, BB),         256>>>(wo, gamma);

    cudaStreamWaitEvent(0, ev_join, 0);
    k_wg_out  <<<dim3(16, 16, BB),       256>>>(conv_b, out);
}

// round 14
// speedup vs baseline: 4.1507x; 1.6371x over previous
#include <cuda_runtime.h>
#include <math.h>
#include <stdint.h>

#define BB     16
#define CC     256
#define HH     64
#define WWID   64
#define PP     4096   // HH*WWID
#define TT     1024   // 32*32 pooled tokens
#define NHEADS 8
#define DHEAD  32
#define NTIL   4096   // 16 b * 256 tiles (16x16 tiles of 4x4 outputs)

// ---------------- scratch (device globals; no allocs allowed) ----------------
__device__ float         g_pooled[BB*CC*TT];           // [b][c][t]
__device__ unsigned char g_idx   [BB*CC*TT];           // argmax 0..3
__device__ float         g_q   [BB*NHEADS*DHEAD*TT];   // [bh][dhi][t]
__device__ float         g_k   [BB*NHEADS*DHEAD*TT];
__device__ float         g_v   [BB*NHEADS*DHEAD*TT];
__device__ float         g_attn[BB*NHEADS*DHEAD*TT];   // [bh][dhi][t]
__device__ float         g_proj[BB*CC*TT];             // [b][c][t], pre-scaled by tanh(gamma)
__device__ float         g_U[36*CC*CC];                // [p][ic][oc]
__device__ float         g_V[36*CC*NTIL];              // [p][ic][tile]
__device__ float         g_M[36*CC*NTIL];              // [p][oc][tile]

// ---------------- tf32 mma helpers (fragment mapping validated R13) ---------
__device__ __forceinline__ float f2tf(float v) {
    uint32_t u;
    asm("cvt.rna.tf32.f32 %0, %1;" : "=r"(u) : "f"(v));
    return __uint_as_float(u);
}
__device__ __forceinline__ void mma_tf32(float4& c, const uint32_t* a, uint2 b) {
    asm volatile(
        "mma.sync.aligned.m16n8k8.row.col.f32.tf32.tf32.f32 "
        "{%0,%1,%2,%3}, {%4,%5,%6,%7}, {%8,%9}, {%0,%1,%2,%3};"
        : "+f"(c.x), "+f"(c.y), "+f"(c.z), "+f"(c.w)
        : "r"(a[0]), "r"(a[1]), "r"(a[2]), "r"(a[3]), "r"(b.x), "r"(b.y));
}

// =====================================================================
// Kernel 1: 1x1 conv (feature reduce) + bias + 2x2 maxpool with indices
// (fp32 — argmax indices are discrete, must match reference exactly)
// =====================================================================
__global__ __launch_bounds__(256) void k_fr_pool(
    const float* __restrict__ x, const float* __restrict__ frw,
    const float* __restrict__ frb)
{
    __shared__ float Xs[32][128];
    __shared__ float Ws[64][32];
    int tid = threadIdx.x;
    int hp = blockIdx.x, ocT = blockIdx.y, b = blockIdx.z;
    int oc0 = ocT * 64;
    int ocg = tid >> 5;
    int pxg = tid & 31;

    float acc[8][4];
#pragma unroll
    for (int i = 0; i < 8; i++)
#pragma unroll
        for (int j = 0; j < 4; j++) acc[i][j] = 0.f;

    const float* xb = x + (size_t)b*CC*PP + hp*128;

    for (int c0 = 0; c0 < CC; c0 += 32) {
#pragma unroll
        for (int j = 0; j < 4; j++) {
            int f = tid + j*256;
            int k = f >> 5, c4 = f & 31;
            *(float4*)&Xs[k][c4*4] = *(const float4*)(xb + (size_t)(c0+k)*PP + c4*4);
        }
#pragma unroll
        for (int j = 0; j < 8; j++) {
            int f = tid + j*256;
            int oc = f >> 5, k = f & 31;
            Ws[oc][k] = frw[(size_t)(oc0+oc)*CC + c0 + k];
        }
        __syncthreads();
#pragma unroll 8
        for (int k = 0; k < 32; k++) {
            float4 xv = *(const float4*)&Xs[k][pxg*4];
#pragma unroll
            for (int i = 0; i < 8; i++) {
                float w = Ws[ocg*8+i][k];
                acc[i][0] = fmaf(w, xv.x, acc[i][0]);
                acc[i][1] = fmaf(w, xv.y, acc[i][1]);
                acc[i][2] = fmaf(w, xv.z, acc[i][2]);
                acc[i][3] = fmaf(w, xv.w, acc[i][3]);
            }
        }
        __syncthreads();
    }

    bool low = (pxg < 16);
#pragma unroll
    for (int i = 0; i < 8; i++) {
        int oc = oc0 + ocg*8 + i;
        float bi = frb[oc];
        float a0 = acc[i][0]+bi, a1 = acc[i][1]+bi;
        float a2 = acc[i][2]+bi, a3 = acc[i][3]+bi;
        float p0 = __shfl_xor_sync(0xffffffffu, a0, 16);
        float p1 = __shfl_xor_sync(0xffffffffu, a1, 16);
        float p2 = __shfl_xor_sync(0xffffffffu, a2, 16);
        float p3 = __shfl_xor_sync(0xffffffffu, a3, 16);
        if (low) {
            size_t base = ((size_t)b*CC + oc)*TT + hp*32 + pxg*2;
            {   float best = a0; int am = 0;
                if (a1 > best) { best = a1; am = 1; }
                if (p0 > best) { best = p0; am = 2; }
                if (p1 > best) { best = p1; am = 3; }
                g_pooled[base] = best; g_idx[base] = (unsigned char)am; }
            {   float best = a2; int am = 0;
                if (a3 > best) { best = a3; am = 1; }
                if (p2 > best) { best = p2; am = 2; }
                if (p3 > best) { best = p3; am = 3; }
                g_pooled[base+1] = best; g_idx[base+1] = (unsigned char)am; }
        }
    }
}

// =====================================================================
// Kernel 2: QKV projection via mma.sync tf32 (unchanged from R13)
// =====================================================================
__global__ __launch_bounds__(256, 2) void k_qkv_mma(
    const float* __restrict__ wq, const float* __restrict__ wk,
    const float* __restrict__ wv)
{
    __shared__ float As[2][2][64][8];   // [stage][kslice][m][2c+hi], k = c+hi*4
    __shared__ float Bs[2][16][136];    // [stage][k][n], pad 8 -> conflict-free
    int tid = threadIdx.x;
    int lane = tid & 31, w = tid >> 5;
    int r = lane >> 2, cq = lane & 3;
    int wm = w >> 2, wn = w & 3;
    int t0 = blockIdx.x * 128;
    int mat = blockIdx.y >> 2, dT = blockIdx.y & 3;
    int b = blockIdx.z;
    int m0 = dT * 64;

    const float* W  = (mat == 0) ? wq : (mat == 1) ? wk : wv;
    const float* Bg = g_pooled + (size_t)b*CC*TT;

    int a_kk = tid >> 4, a_m = (tid & 15) * 4;
    int a_col = ((a_kk & 3) << 1) | ((a_kk >> 2) & 1);
    int a_ks  = a_kk >> 3;
    int b_kk0 = tid >> 5,        b_tq0 = (tid & 31) * 4;
    int b_kk1 = (tid >> 5) + 8,  b_tq1 = b_tq0;

    float4 acc[2][4];
#pragma unroll
    for (int mt = 0; mt < 2; mt++)
#pragma unroll
        for (int nt = 0; nt < 4; nt++) acc[mt][nt] = make_float4(0.f,0.f,0.f,0.f);

    float4 ra, rb0, rb1;
    ra  = *(const float4*)(W  + (size_t)a_kk*CC + m0 + a_m);
    rb0 = *(const float4*)(Bg + (size_t)b_kk0*TT + t0 + b_tq0);
    rb1 = *(const float4*)(Bg + (size_t)b_kk1*TT + t0 + b_tq1);
    As[0][a_ks][a_m+0][a_col] = f2tf(ra.x);
    As[0][a_ks][a_m+1][a_col] = f2tf(ra.y);
    As[0][a_ks][a_m+2][a_col] = f2tf(ra.z);
    As[0][a_ks][a_m+3][a_col] = f2tf(ra.w);
    *(float4*)&Bs[0][b_kk0][b_tq0] = make_float4(f2tf(rb0.x), f2tf(rb0.y), f2tf(rb0.z), f2tf(rb0.w));
    *(float4*)&Bs[0][b_kk1][b_tq1] = make_float4(f2tf(rb1.x), f2tf(rb1.y), f2tf(rb1.z), f2tf(rb1.w));
    __syncthreads();
    ra  = *(const float4*)(W  + (size_t)(16 + a_kk)*CC + m0 + a_m);
    rb0 = *(const float4*)(Bg + (size_t)(16 + b_kk0)*TT + t0 + b_tq0);
    rb1 = *(const float4*)(Bg + (size_t)(16 + b_kk1)*TT + t0 + b_tq1);

    for (int s = 0; s < 16; s++) {
        int cur = s & 1;
#pragma unroll
        for (int ks = 0; ks < 2; ks++) {
            uint32_t a[2][4];
#pragma unroll
            for (int mt = 0; mt < 2; mt++) {
                int mb = wm*32 + mt*16;
                float2 lo = *(const float2*)&As[cur][ks][mb + r][cq*2];
                float2 hi = *(const float2*)&As[cur][ks][mb + r + 8][cq*2];
                a[mt][0] = __float_as_uint(lo.x); a[mt][1] = __float_as_uint(hi.x);
                a[mt][2] = __float_as_uint(lo.y); a[mt][3] = __float_as_uint(hi.y);
            }
#pragma unroll
            for (int nt = 0; nt < 4; nt++) {
                int nb = wn*32 + nt*8 + r;
                uint2 bf;
                bf.x = __float_as_uint(Bs[cur][ks*8 + cq][nb]);
                bf.y = __float_as_uint(Bs[cur][ks*8 + cq + 4][nb]);
                mma_tf32(acc[0][nt], a[0], bf);
                mma_tf32(acc[1][nt], a[1], bf);
            }
        }
        if (s < 15) {
            __syncthreads();
            int nxt = cur ^ 1;
            As[nxt][a_ks][a_m+0][a_col] = f2tf(ra.x);
            As[nxt][a_ks][a_m+1][a_col] = f2tf(ra.y);
            As[nxt][a_ks][a_m+2][a_col] = f2tf(ra.z);
            As[nxt][a_ks][a_m+3][a_col] = f2tf(ra.w);
            *(float4*)&Bs[nxt][b_kk0][b_tq0] = make_float4(f2tf(rb0.x), f2tf(rb0.y), f2tf(rb0.z), f2tf(rb0.w));
            *(float4*)&Bs[nxt][b_kk1][b_tq1] = make_float4(f2tf(rb1.x), f2tf(rb1.y), f2tf(rb1.z), f2tf(rb1.w));
            if (s < 14) {
                int k0 = (s + 2) * 16;
                ra  = *(const float4*)(W  + (size_t)(k0 + a_kk)*CC + m0 + a_m);
                rb0 = *(const float4*)(Bg + (size_t)(k0 + b_kk0)*TT + t0 + b_tq0);
                rb1 = *(const float4*)(Bg + (size_t)(k0 + b_kk1)*TT + t0 + b_tq1);
            }
            __syncthreads();
        }
    }

    float* O = (mat == 0) ? g_q : (mat == 1) ? g_k : g_v;
#pragma unroll
    for (int mt = 0; mt < 2; mt++) {
        int dbase = m0 + wm*32 + mt*16;
#pragma unroll
        for (int nt = 0; nt < 4; nt++) {
            float4 c = acc[mt][nt];
            int t  = t0 + wn*32 + nt*8 + cq*2;
            int d1 = dbase + r, d2 = dbase + r + 8;
            size_t a1 = (((size_t)b*NHEADS + (d1 & 7))*DHEAD + (d1 >> 3))*TT + t;
            size_t a2 = (((size_t)b*NHEADS + (d2 & 7))*DHEAD + (d2 >> 3))*TT + t;
            *(float2*)&O[a1] = make_float2(c.x, c.y);
            *(float2*)&O[a2] = make_float2(c.z, c.w);
        }
    }
}

// =====================================================================
// Kernel 3: flash attention via mma.sync tf32 + fp32 online softmax.
// Block = 128 q (4 warps, warp = 32 q = 2 m-tiles), K-chunk = 32.
// Q staged transposed [q][d]; K direct [d][key]; V transposed [key][d].
// All fragment LDS patterns conflict-free (A: 4r+cq / 8r+cq; B: 8cq+r).
// Grid (8 qT, 128 bh), 128 threads.
// =====================================================================
__global__ __launch_bounds__(128) void k_attn_mma()
{
    __shared__ float Qs[128][36];      // [q][d], stride 36 (≡4 mod 32)
    __shared__ float Ks[32][40];       // [d][key], stride 40 (≡8)
    __shared__ float Vs[32][40];       // [key][d], stride 40 (≡8)
    __shared__ float Ps[4][32][36];    // per-warp P [q][key], stride 36

    int tid = threadIdx.x;
    int lane = tid & 31, w = tid >> 5;
    int r = lane >> 2, cq = lane & 3;
    int q0 = blockIdx.x * 128;
    int bh = blockIdx.y;
    const float* Qg = g_q + (size_t)bh*DHEAD*TT;
    const float* Kg = g_k + (size_t)bh*DHEAD*TT;
    const float* Vg = g_v + (size_t)bh*DHEAD*TT;
    const float qscale = 0.17677669529663687f;  // 1/sqrt(32)

    // stage Q once: [d][q]-major gmem -> [q][d] smem, pre-scaled, tf32
#pragma unroll
    for (int j = 0; j < 8; j++) {
        int e = tid + j*128;
        int d = e >> 5, q4 = (e & 31) * 4;
        float4 v = *(const float4*)(Qg + (size_t)d*TT + q0 + q4);
        Qs[q4+0][d] = f2tf(v.x * qscale);
        Qs[q4+1][d] = f2tf(v.y * qscale);
        Qs[q4+2][d] = f2tf(v.z * qscale);
        Qs[q4+3][d] = f2tf(v.w * qscale);
    }

    float mrow[2][2], lrow[2][2];
#pragma unroll
    for (int mt = 0; mt < 2; mt++) {
        mrow[mt][0] = -3.0e38f; mrow[mt][1] = -3.0e38f;
        lrow[mt][0] = 0.f;      lrow[mt][1] = 0.f;
    }
    float4 of[2][4];
#pragma unroll
    for (int mt = 0; mt < 2; mt++)
#pragma unroll
        for (int nt = 0; nt < 4; nt++) of[mt][nt] = make_float4(0.f,0.f,0.f,0.f);

    for (int k0 = 0; k0 < TT; k0 += 32) {
        // stage K (direct) + V (transposed), tf32
#pragma unroll
        for (int j = 0; j < 2; j++) {
            int e = tid + j*128;
            int d = e >> 3, c4 = (e & 7) * 4;
            float4 kv = *(const float4*)(Kg + (size_t)d*TT + k0 + c4);
            Ks[d][c4+0] = f2tf(kv.x); Ks[d][c4+1] = f2tf(kv.y);
            Ks[d][c4+2] = f2tf(kv.z); Ks[d][c4+3] = f2tf(kv.w);
            float4 vv = *(const float4*)(Vg + (size_t)d*TT + k0 + c4);
            Vs[c4+0][d] = f2tf(vv.x); Vs[c4+1][d] = f2tf(vv.y);
            Vs[c4+2][d] = f2tf(vv.z); Vs[c4+3][d] = f2tf(vv.w);
        }
        __syncthreads();

        // ---- S = Q K^T  (m=q 32, n=key 32, k=d 32)
        float4 s[2][4];
#pragma unroll
        for (int mt = 0; mt < 2; mt++)
#pragma unroll
            for (int nt = 0; nt < 4; nt++) s[mt][nt] = make_float4(0.f,0.f,0.f,0.f);
#pragma unroll
        for (int ks = 0; ks < 4; ks++) {
            uint32_t a[2][4];
#pragma unroll
            for (int mt = 0; mt < 2; mt++) {
                int mb = w*32 + mt*16;
                a[mt][0] = __float_as_uint(Qs[mb + r    ][ks*8 + cq]);
                a[mt][1] = __float_as_uint(Qs[mb + r + 8][ks*8 + cq]);
                a[mt][2] = __float_as_uint(Qs[mb + r    ][ks*8 + cq + 4]);
                a[mt][3] = __float_as_uint(Qs[mb + r + 8][ks*8 + cq + 4]);
            }
#pragma unroll
            for (int nt = 0; nt < 4; nt++) {
                uint2 bf;
                bf.x = __float_as_uint(Ks[ks*8 + cq    ][nt*8 + r]);
                bf.y = __float_as_uint(Ks[ks*8 + cq + 4][nt*8 + r]);
                mma_tf32(s[0][nt], a[0], bf);
                mma_tf32(s[1][nt], a[1], bf);
            }
        }

        // ---- online softmax (fp32), write P (tf32) to per-warp smem
#pragma unroll
        for (int mt = 0; mt < 2; mt++) {
            float vm0 = -3.0e38f, vm1 = -3.0e38f;
#pragma unroll
            for (int nt = 0; nt < 4; nt++) {
                vm0 = fmaxf(vm0, fmaxf(s[mt][nt].x, s[mt][nt].y));
                vm1 = fmaxf(vm1, fmaxf(s[mt][nt].z, s[mt][nt].w));
            }
            vm0 = fmaxf(vm0, __shfl_xor_sync(0xffffffffu, vm0, 1));
            vm0 = fmaxf(vm0, __shfl_xor_sync(0xffffffffu, vm0, 2));
            vm1 = fmaxf(vm1, __shfl_xor_sync(0xffffffffu, vm1, 1));
            vm1 = fmaxf(vm1, __shfl_xor_sync(0xffffffffu, vm1, 2));
            float mn0 = fmaxf(mrow[mt][0], vm0);
            float mn1 = fmaxf(mrow[mt][1], vm1);
            float al0 = __expf(mrow[mt][0] - mn0);
            float al1 = __expf(mrow[mt][1] - mn1);
            float sum0 = 0.f, sum1 = 0.f;
            int rowa = mt*16 + r, rowb = rowa + 8;
#pragma unroll
            for (int nt = 0; nt < 4; nt++) {
                float p00 = __expf(s[mt][nt].x - mn0);
                float p01 = __expf(s[mt][nt].y - mn0);
                float p10 = __expf(s[mt][nt].z - mn1);
                float p11 = __expf(s[mt][nt].w - mn1);
                Ps[w][rowa][nt*8 + cq*2]     = f2tf(p00);
                Ps[w][rowa][nt*8 + cq*2 + 1] = f2tf(p01);
                Ps[w][rowb][nt*8 + cq*2]     = f2tf(p10);
                Ps[w][rowb][nt*8 + cq*2 + 1] = f2tf(p11);
                sum0 += p00 + p01;
                sum1 += p10 + p11;
            }
            sum0 += __shfl_xor_sync(0xffffffffu, sum0, 1);
            sum0 += __shfl_xor_sync(0xffffffffu, sum0, 2);
            sum1 += __shfl_xor_sync(0xffffffffu, sum1, 1);
            sum1 += __shfl_xor_sync(0xffffffffu, sum1, 2);
            lrow[mt][0] = lrow[mt][0]*al0 + sum0;  mrow[mt][0] = mn0;
            lrow[mt][1] = lrow[mt][1]*al1 + sum1;  mrow[mt][1] = mn1;
#pragma unroll
            for (int nt = 0; nt < 4; nt++) {
                of[mt][nt].x *= al0; of[mt][nt].y *= al0;
                of[mt][nt].z *= al1; of[mt][nt].w *= al1;
            }
        }
        __syncwarp();

        // ---- O += P V  (m=q 32, n=d 32, k=key 32)
#pragma unroll
        for (int ks = 0; ks < 4; ks++) {
            uint32_t a[2][4];
#pragma unroll
            for (int mt = 0; mt < 2; mt++) {
                int mb = mt*16;
                a[mt][0] = __float_as_uint(Ps[w][mb + r    ][ks*8 + cq]);
                a[mt][1] = __float_as_uint(Ps[w][mb + r + 8][ks*8 + cq]);
                a[mt][2] = __float_as_uint(Ps[w][mb + r    ][ks*8 + cq + 4]);
                a[mt][3] = __float_as_uint(Ps[w][mb + r + 8][ks*8 + cq + 4]);
            }
#pragma unroll
            for (int nt = 0; nt < 4; nt++) {
                uint2 bf;
                bf.x = __float_as_uint(Vs[ks*8 + cq    ][nt*8 + r]);
                bf.y = __float_as_uint(Vs[ks*8 + cq + 4][nt*8 + r]);
                mma_tf32(of[0][nt], a[0], bf);
                mma_tf32(of[1][nt], a[1], bf);
            }
        }
        __syncthreads();
    }

    // epilogue: O normalized by 1/l, written to g_attn [bh][d][t]
    float* Og = g_attn + (size_t)bh*DHEAD*TT;
#pragma unroll
    for (int mt = 0; mt < 2; mt++) {
        float li0 = 1.f / lrow[mt][0];
        float li1 = 1.f / lrow[mt][1];
        int qr = q0 + w*32 + mt*16 + r;
#pragma unroll
        for (int nt = 0; nt < 4; nt++) {
            float4 c = of[mt][nt];
            int d0 = nt*8 + cq*2;
            Og[(size_t)d0*TT + qr]           = c.x * li0;
            Og[(size_t)(d0+1)*TT + qr]       = c.y * li0;
            Og[(size_t)d0*TT + qr + 8]       = c.z * li1;
            Og[(size_t)(d0+1)*TT + qr + 8]   = c.w * li1;
        }
    }
}

// =====================================================================
// Kernel 4: output projection via mma.sync tf32 (unchanged from R13)
// =====================================================================
__global__ __launch_bounds__(256, 2) void k_proj_mma(
    const float* __restrict__ wo, const float* __restrict__ gamma)
{
    __shared__ float As[2][2][64][8];
    __shared__ float Bs[2][16][136];
    int tid = threadIdx.x;
    int lane = tid & 31, w = tid >> 5;
    int r = lane >> 2, cq = lane & 3;
    int wm = w >> 2, wn = w & 3;
    int t0 = blockIdx.x * 128;
    int dT = blockIdx.y;
    int b = blockIdx.z;
    int m0 = dT * 64;

    int a_kk = tid >> 4, a_m = (tid & 15) * 4;
    int a_col = ((a_kk & 3) << 1) | ((a_kk >> 2) & 1);
    int a_ks  = a_kk >> 3;
    int b_kk0 = tid >> 5,       b_tq0 = (tid & 31) * 4;
    int b_kk1 = (tid >> 5) + 8, b_tq1 = b_tq0;

    #define ATTN_ROW(c) (g_attn + (((size_t)b*NHEADS + ((c) & 7))*DHEAD + ((c) >> 3))*TT)

    float4 acc[2][4];
#pragma unroll
    for (int mt = 0; mt < 2; mt++)
#pragma unroll
        for (int nt = 0; nt < 4; nt++) acc[mt][nt] = make_float4(0.f,0.f,0.f,0.f);

    float4 ra, rb0, rb1;
    ra  = *(const float4*)(wo + (size_t)a_kk*CC + m0 + a_m);
    rb0 = *(const float4*)(ATTN_ROW(b_kk0) + t0 + b_tq0);
    rb1 = *(const float4*)(ATTN_ROW(b_kk1) + t0 + b_tq1);
    As[0][a_ks][a_m+0][a_col] = f2tf(ra.x);
    As[0][a_ks][a_m+1][a_col] = f2tf(ra.y);
    As[0][a_ks][a_m+2][a_col] = f2tf(ra.z);
    As[0][a_ks][a_m+3][a_col] = f2tf(ra.w);
    *(float4*)&Bs[0][b_kk0][b_tq0] = make_float4(f2tf(rb0.x), f2tf(rb0.y), f2tf(rb0.z), f2tf(rb0.w));
    *(float4*)&Bs[0][b_kk1][b_tq1] = make_float4(f2tf(rb1.x), f2tf(rb1.y), f2tf(rb1.z), f2tf(rb1.w));
    __syncthreads();
    ra  = *(const float4*)(wo + (size_t)(16 + a_kk)*CC + m0 + a_m);
    rb0 = *(const float4*)(ATTN_ROW(16 + b_kk0) + t0 + b_tq0);
    rb1 = *(const float4*)(ATTN_ROW(16 + b_kk1) + t0 + b_tq1);

    for (int s = 0; s < 16; s++) {
        int cur = s & 1;
#pragma unroll
        for (int ks = 0; ks < 2; ks++) {
            uint32_t a[2][4];
#pragma unroll
            for (int mt = 0; mt < 2; mt++) {
                int mb = wm*32 + mt*16;
                float2 lo = *(const float2*)&As[cur][ks][mb + r][cq*2];
                float2 hi = *(const float2*)&As[cur][ks][mb + r + 8][cq*2];
                a[mt][0] = __float_as_uint(lo.x); a[mt][1] = __float_as_uint(hi.x);
                a[mt][2] = __float_as_uint(lo.y); a[mt][3] = __float_as_uint(hi.y);
            }
#pragma unroll
            for (int nt = 0; nt < 4; nt++) {
                int nb = wn*32 + nt*8 + r;
                uint2 bf;
                bf.x = __float_as_uint(Bs[cur][ks*8 + cq][nb]);
                bf.y = __float_as_uint(Bs[cur][ks*8 + cq + 4][nb]);
                mma_tf32(acc[0][nt], a[0], bf);
                mma_tf32(acc[1][nt], a[1], bf);
            }
        }
        if (s < 15) {
            __syncthreads();
            int nxt = cur ^ 1;
            As[nxt][a_ks][a_m+0][a_col] = f2tf(ra.x);
            As[nxt][a_ks][a_m+1][a_col] = f2tf(ra.y);
            As[nxt][a_ks][a_m+2][a_col] = f2tf(ra.z);
            As[nxt][a_ks][a_m+3][a_col] = f2tf(ra.w);
            *(float4*)&Bs[nxt][b_kk0][b_tq0] = make_float4(f2tf(rb0.x), f2tf(rb0.y), f2tf(rb0.z), f2tf(rb0.w));
            *(float4*)&Bs[nxt][b_kk1][b_tq1] = make_float4(f2tf(rb1.x), f2tf(rb1.y), f2tf(rb1.z), f2tf(rb1.w));
            if (s < 14) {
                int k0 = (s + 2) * 16;
                ra  = *(const float4*)(wo + (size_t)(k0 + a_kk)*CC + m0 + a_m);
                rb0 = *(const float4*)(ATTN_ROW(k0 + b_kk0) + t0 + b_tq0);
                rb1 = *(const float4*)(ATTN_ROW(k0 + b_kk1) + t0 + b_tq1);
            }
            __syncthreads();
        }
    }
    #undef ATTN_ROW

    float tg = tanhf(gamma[0]);
#pragma unroll
    for (int mt = 0; mt < 2; mt++) {
        int dbase = m0 + wm*32 + mt*16;
#pragma unroll
        for (int nt = 0; nt < 4; nt++) {
            float4 c = acc[mt][nt];
            int t  = t0 + wn*32 + nt*8 + cq*2;
            size_t a1 = ((size_t)b*CC + dbase + r)*TT + t;
            size_t a2 = ((size_t)b*CC + dbase + r + 8)*TT + t;
            *(float2*)&g_proj[a1] = make_float2(c.x*tg, c.y*tg);
            *(float2*)&g_proj[a2] = make_float2(c.z*tg, c.w*tg);
        }
    }
}

// =====================================================================
// Winograd F(4x4, 3x3)  (unchanged — fp32)
// =====================================================================
__device__ __forceinline__ void gfilt(const float a, const float b, const float c,
                                      float* o) {
    o[0] = 0.25f*a;
    o[1] = (-a - b - c) * (1.f/6.f);
    o[2] = (-a + b - c) * (1.f/6.f);
    o[3] = a*(1.f/24.f) + b*(1.f/12.f) + c*(1.f/6.f);
    o[4] = a*(1.f/24.f) - b*(1.f/12.f) + c*(1.f/6.f);
    o[5] = c;
}

__global__ __launch_bounds__(256) void k_wg_wt(const float* __restrict__ cw)
{
    int idx = blockIdx.x*256 + threadIdx.x;
    int oc = idx & 255, ic = idx >> 8;
    const float* g = cw + (size_t)oc*2304 + ic*9;
    float g00=g[0],g01=g[1],g02=g[2],g10=g[3],g11=g[4],g12=g[5],g20=g[6],g21=g[7],g22=g[8];

    float t[6][3];
    {
        float o0[6], o1[6], o2[6];
        gfilt(g00, g10, g20, o0);
        gfilt(g01, g11, g21, o1);
        gfilt(g02, g12, g22, o2);
#pragma unroll
        for (int r = 0; r < 6; r++) { t[r][0]=o0[r]; t[r][1]=o1[r]; t[r][2]=o2[r]; }
    }
#pragma unroll
    for (int r = 0; r < 6; r++) {
        float o[6];
        gfilt(t[r][0], t[r][1], t[r][2], o);
#pragma unroll
        for (int c = 0; c < 6; c++)
            g_U[(size_t)(r*6+c)*CC*CC + (size_t)ic*CC + oc] = o[c];
    }
}

__device__ __forceinline__ void btrans(const float* d, float* o) {
    o[0] = 4.f*d[0] - 5.f*d[2] + d[4];
    o[1] = -4.f*d[1] - 4.f*d[2] + d[3] + d[4];
    o[2] =  4.f*d[1] - 4.f*d[2] - d[3] + d[4];
    o[3] = -2.f*d[1] -     d[2] + 2.f*d[3] + d[4];
    o[4] =  2.f*d[1] -     d[2] - 2.f*d[3] + d[4];
    o[5] =  4.f*d[1] - 5.f*d[3] + d[5];
}

__global__ __launch_bounds__(256) void k_wg_in(const float* __restrict__ x)
{
    int tid = threadIdx.x;
    int tx = tid & 15, ic_l = tid >> 4;
    int ty = blockIdx.x, icT = blockIdx.y, b = blockIdx.z;
    int ic = icT*16 + ic_l;
    int tile = b*256 + ty*16 + tx;

    const float* xp = x + ((size_t)b*CC + ic)*PP;
    int gy0 = ty*4 - 1, gx0 = tx*4 - 1;

    float d[6][6];
#pragma unroll
    for (int i = 0; i < 6; i++) {
        int gy = gy0 + i;
        bool yok = (unsigned)gy < 64u;
#pragma unroll
        for (int j = 0; j < 6; j++) {
            int gx = gx0 + j;
            d[i][j] = (yok && (unsigned)gx < 64u) ? xp[gy*64 + gx] : 0.f;
        }
    }
    float wcol[6][6];
#pragma unroll
    for (int j = 0; j < 6; j++) {
        float col[6] = {d[0][j], d[1][j], d[2][j], d[3][j], d[4][j], d[5][j]};
        float o[6];
        btrans(col, o);
#pragma unroll
        for (int r = 0; r < 6; r++) wcol[r][j] = o[r];
    }
#pragma unroll
    for (int r = 0; r < 6; r++) {
        float o[6];
        btrans(wcol[r], o);
#pragma unroll
        for (int c = 0; c < 6; c++)
            g_V[(size_t)(r*6+c)*CC*NTIL + (size_t)ic*NTIL + tile] = o[c];
    }
}

__global__ __launch_bounds__(256) void k_wg_gemm()
{
    __shared__ float As[32][64];
    __shared__ float Bs[32][64];
    int tid = threadIdx.x;
    int t0 = blockIdx.x*64, oc0 = blockIdx.y*64, p = blockIdx.z;
    int ng = tid & 15, mg = tid >> 4;

    const float* Vp = g_V + (size_t)p*CC*NTIL;
    const float* Up = g_U + (size_t)p*CC*CC;

    float acc[4][4];
#pragma unroll
    for (int i = 0; i < 4; i++)
#pragma unroll
        for (int j = 0; j < 4; j++) acc[i][j] = 0.f;

    for (int c0 = 0; c0 < CC; c0 += 32) {
#pragma unroll
        for (int j = 0; j < 2; j++) {
            int f = tid + j*256;
            int k = f >> 4, m4 = f & 15;
            *(float4*)&As[k][m4*4] = *(const float4*)(Vp + (size_t)(c0+k)*NTIL + t0 + m4*4);
            *(float4*)&Bs[k][m4*4] = *(const float4*)(Up + (size_t)(c0+k)*CC + oc0 + m4*4);
        }
        __syncthreads();
#pragma unroll 8
        for (int k = 0; k < 32; k++) {
            float4 a  = *(const float4*)&As[k][mg*4];
            float4 bv = *(const float4*)&Bs[k][ng*4];
            float am[4] = {a.x,a.y,a.z,a.w};
            float bn[4] = {bv.x,bv.y,bv.z,bv.w};
#pragma unroll
            for (int mm = 0; mm < 4; mm++)
#pragma unroll
                for (int nn = 0; nn < 4; nn++)
                    acc[mm][nn] = fmaf(am[mm], bn[nn], acc[mm][nn]);
        }
        __syncthreads();
    }

    float* Mp = g_M + (size_t)p*CC*NTIL;
#pragma unroll
    for (int nn = 0; nn < 4; nn++) {
        int oc = oc0 + ng*4 + nn;
        *(float4*)(Mp + (size_t)oc*NTIL + t0 + mg*4) =
            make_float4(acc[0][nn], acc[1][nn], acc[2][nn], acc[3][nn]);
    }
}

__device__ __forceinline__ void atrans(const float* w, float* o) {
    o[0] = w[0] + w[1] + w[2] + w[3] + w[4];
    o[1] = w[1] - w[2] + 2.f*w[3] - 2.f*w[4];
    o[2] = w[1] + w[2] + 4.f*w[3] + 4.f*w[4];
    o[3] = w[1] - w[2] + 8.f*w[3] - 8.f*w[4] + w[5];
}

__global__ __launch_bounds__(256) void k_wg_out(
    const float* __restrict__ cb, float* __restrict__ out)
{
    int tid = threadIdx.x;
    int tx = tid & 15, oc_l = tid >> 4;
    int ty = blockIdx.x, ocT = blockIdx.y, b = blockIdx.z;
    int oc = ocT*16 + oc_l;
    int tile = b*256 + ty*16 + tx;

    float m[6][6];
#pragma unroll
    for (int r = 0; r < 6; r++)
#pragma unroll
        for (int c = 0; c < 6; c++)
            m[r][c] = g_M[(size_t)(r*6+c)*CC*NTIL + (size_t)oc*NTIL + tile];

    float z[4][6];
#pragma unroll
    for (int j = 0; j < 6; j++) {
        float col[6] = {m[0][j], m[1][j], m[2][j], m[3][j], m[4][j], m[5][j]};
        float o[4];
        atrans(col, o);
#pragma unroll
        for (int i = 0; i < 4; i++) z[i][j] = o[i];
    }

    float bias = cb[oc];
    size_t chan = (size_t)b*CC + oc;
    const unsigned char* idxp  = g_idx  + chan*TT;
    const float*         projp = g_proj + chan*TT;
    float* op = out + chan*PP;

#pragma unroll
    for (int r = 0; r < 4; r++) {
        float y[4];
        atrans(z[r], y);
        int gy = ty*4 + r;
        int h2 = gy >> 1;
        int subr = (gy & 1) << 1;
        float v[4];
#pragma unroll
        for (int c = 0; c < 4; c++) {
            int gx = tx*4 + c;
            float vv = y[c] + bias;
            int w2 = gx >> 1;
            if (idxp[h2*32 + w2] == (unsigned char)(subr | (gx & 1)))
                vv += projp[h2*32 + w2];
            v[c] = vv;
        }
        *(float4*)(op + (size_t)gy*64 + tx*4) = make_float4(v[0], v[1], v[2], v[3]);
    }
}

// =====================================================================
extern "C" void kernel_launch(void* const* d_in, const int* in_sizes, int n_in,
                              void* d_out, int out_size)
{
    const float* x      = (const float*)d_in[0];
    const float* conv_w = (const float*)d_in[1];
    const float* conv_b = (const float*)d_in[2];
    const float* fr_w   = (const float*)d_in[3];
    const float* fr_b   = (const float*)d_in[4];
    const float* wq     = (const float*)d_in[5];
    const float* wk     = (const float*)d_in[6];
    const float* wv     = (const float*)d_in[7];
    const float* wo     = (const float*)d_in[8];
    const float* gamma  = (const float*)d_in[9];
    float* out = (float*)d_out;

    static cudaStream_t s1 = [](){
        cudaStream_t s; cudaStreamCreateWithFlags(&s, cudaStreamNonBlocking); return s; }();
    static cudaEvent_t ev_fork = [](){
        cudaEvent_t e; cudaEventCreateWithFlags(&e, cudaEventDisableTiming); return e; }();
    static cudaEvent_t ev_join = [](){
        cudaEvent_t e; cudaEventCreateWithFlags(&e, cudaEventDisableTiming); return e; }();

    cudaEventRecord(ev_fork, 0);
    cudaStreamWaitEvent(s1, ev_fork, 0);

    k_wg_wt   <<<256, 256, 0, s1>>>(conv_w);
    k_wg_in   <<<dim3(16, 16, BB),       256, 0, s1>>>(x);
    k_wg_gemm <<<dim3(64, 4, 36),        256, 0, s1>>>();
    cudaEventRecord(ev_join, s1);

    k_fr_pool  <<<dim3(32, 4, BB),        256>>>(x, fr_w, fr_b);
    k_qkv_mma  <<<dim3(8, 12, BB),        256>>>(wq, wk, wv);
    k_attn_mma <<<dim3(8, BB*NHEADS, 1),  128>>>();
    k_proj_mma <<<dim3(8, 4, BB),         256>>>(wo, gamma);

    cudaStreamWaitEvent(0, ev_join, 0);
    k_wg_out  <<<dim3(16, 16, BB),       256>>>(conv_b, out);
}